// round 1
// baseline (speedup 1.0000x reference)
#include <cuda_runtime.h>
#include <math.h>

// Problem constants
#define NPTS   30000
#define CDIM   128
#define SDIM   16      // neighbors
#define HDIM   8       // heads
#define DDIM   16      // dims per head
#define OSDIM  16      // O / SHARE
#define EPSLN  1e-5f

// Scratch for q,k,v (no cudaMalloc allowed)
__device__ float g_q[NPTS * CDIM];
__device__ float g_k[NPTS * CDIM];
__device__ float g_v[NPTS * CDIM];

// ---------------------------------------------------------------------------
// QKV GEMM: out = x @ W + b   (30000x128 @ 128x128), three matrices via grid.y
// Block: 256 threads, 32 rows x 128 cols per block.
// ---------------------------------------------------------------------------
__global__ __launch_bounds__(256) void qkv_gemm(
    const float* __restrict__ x,
    const float* __restrict__ Wq, const float* __restrict__ bq,
    const float* __restrict__ Wk, const float* __restrict__ bk,
    const float* __restrict__ Wv, const float* __restrict__ bv)
{
    const int which = blockIdx.y;
    const float* __restrict__ W    = (which == 0) ? Wq : (which == 1) ? Wk : Wv;
    const float* __restrict__ bias = (which == 0) ? bq : (which == 1) ? bk : bv;
    float* __restrict__ out        = (which == 0) ? g_q : (which == 1) ? g_k : g_v;

    __shared__ float sx[32][128];

    const int tid  = threadIdx.x;
    const int col  = tid & 127;
    const int rh   = tid >> 7;          // 0 or 1
    const int row0 = blockIdx.x * 32;

    // Load 32x128 tile of x (float4 vectorized)
    {
        const float4* xg  = (const float4*)(x + (size_t)row0 * CDIM);
        float4*       sx4 = (float4*)&sx[0][0];
        const int rows_valid = min(32, NPTS - row0);
        const int maxv = rows_valid * 32;   // float4 per row = 32
        for (int i = tid; i < 1024; i += 256)
            sx4[i] = (i < maxv) ? xg[i] : make_float4(0.f, 0.f, 0.f, 0.f);
    }
    __syncthreads();

    float acc[16];
#pragma unroll
    for (int r = 0; r < 16; r++) acc[r] = 0.f;

    const int rbase = rh * 16;
    for (int k = 0; k < 128; k += 4) {
        const float w0 = W[(k + 0) * 128 + col];
        const float w1 = W[(k + 1) * 128 + col];
        const float w2 = W[(k + 2) * 128 + col];
        const float w3 = W[(k + 3) * 128 + col];
#pragma unroll
        for (int r = 0; r < 16; r++) {
            const float4 xv = *(const float4*)&sx[rbase + r][k];  // broadcast
            acc[r] = fmaf(xv.x, w0, acc[r]);
            acc[r] = fmaf(xv.y, w1, acc[r]);
            acc[r] = fmaf(xv.z, w2, acc[r]);
            acc[r] = fmaf(xv.w, w3, acc[r]);
        }
    }

    const float b = bias[col];
#pragma unroll
    for (int r = 0; r < 16; r++) {
        const int n = row0 + rbase + r;
        if (n < NPTS) out[(size_t)n * CDIM + col] = acc[r] + b;
    }
}

// ---------------------------------------------------------------------------
// Fused point-transformer kernel.
// One warp per point; lane owns 4 channels ch4 = lane*4 .. lane*4+3.
// Head group = 4 consecutive lanes (16 channels). Block = 256 thr = 8 points.
// ---------------------------------------------------------------------------
__global__ __launch_bounds__(256) void pt_fused(
    const float* __restrict__ p,
    const int*   __restrict__ idx,
    const float* __restrict__ Wp1, const float* __restrict__ bp1,
    const float* __restrict__ gp,  const float* __restrict__ betap,
    const float* __restrict__ Wp2, const float* __restrict__ bp2,
    const float* __restrict__ gw1, const float* __restrict__ betaw1,
    const float* __restrict__ Ww1, const float* __restrict__ bw1,
    const float* __restrict__ gw2, const float* __restrict__ betaw2,
    const float* __restrict__ Ww2, const float* __restrict__ bw2,
    float* __restrict__ out)
{
    __shared__ float sWw1[16][16];
    __shared__ float sWw2[16][16];
    __shared__ int   sidx[8][SDIM];
    __shared__ float spj [8][SDIM][3];
    __shared__ float sa3 [8][SDIM][3];
    __shared__ float slog[8][SDIM][HDIM];

    const int tid  = threadIdx.x;
    const int pt   = tid >> 5;
    const int lane = tid & 31;
    const int n    = blockIdx.x * 8 + pt;
    const int ch4  = lane * 4;                 // first of 4 channels
    const int d4   = (lane & 3) * 4;           // position within head (d / os)
    const int hh   = lane >> 2;                // head index
    const unsigned FULL = 0xffffffffu;

    // ---- cooperative loads ----
    {   // 16x16 weight matrices (256 floats each, 256 threads)
        float* w1f = &sWw1[0][0];
        float* w2f = &sWw2[0][0];
        w1f[tid] = Ww1[tid];
        w2f[tid] = Ww2[tid];
    }
    if (lane < SDIM) sidx[pt][lane] = idx[n * SDIM + lane];
    __syncwarp();
    for (int t = lane; t < SDIM * 3; t += 32) {
        const int s = t / 3, c = t - 3 * s;
        spj[pt][s][c] = p[(size_t)sidx[pt][s] * 3 + c];
    }
    __syncthreads();   // covers sWw1/sWw2 across warps + spj

    // ---- per-thread hoisted parameters ----
    const float pn0 = p[n * 3 + 0], pn1 = p[n * 3 + 1], pn2 = p[n * 3 + 2];
    float wp1[9], bp1v[3], gpv[3], bepv[3];
#pragma unroll
    for (int i = 0; i < 9; i++) wp1[i] = Wp1[i];
#pragma unroll
    for (int i = 0; i < 3; i++) { bp1v[i] = bp1[i]; gpv[i] = gp[i]; bepv[i] = betap[i]; }

    const float4 xq4   = *(const float4*)(g_q + (size_t)n * CDIM + ch4);
    const float4 wp2c0 = *(const float4*)(Wp2 + 0 * CDIM + ch4);
    const float4 wp2c1 = *(const float4*)(Wp2 + 1 * CDIM + ch4);
    const float4 wp2c2 = *(const float4*)(Wp2 + 2 * CDIM + ch4);
    const float4 bp24  = *(const float4*)(bp2 + ch4);
    const float4 g14   = *(const float4*)(gw1    + d4);
    const float4 be14  = *(const float4*)(betaw1 + d4);
    const float4 b14   = *(const float4*)(bw1    + d4);
    const float4 g24   = *(const float4*)(gw2    + d4);
    const float4 be24  = *(const float4*)(betaw2 + d4);
    const float4 b24   = *(const float4*)(bw2    + d4);

    // ---- pass 1: logits + a3 ----
    int   jn  = sidx[pt][0];
    float4 kg = *(const float4*)(g_k + (size_t)jn * CDIM + ch4);

#pragma unroll 1
    for (int s = 0; s < SDIM; s++) {
        // prefetch next gather
        float4 kgn;
        if (s < SDIM - 1) {
            const int j2 = sidx[pt][s + 1];
            kgn = *(const float4*)(g_k + (size_t)j2 * CDIM + ch4);
        }

        // --- positional branch: a3 (redundant per lane, ~30 flops) ---
        const float pr0 = spj[pt][s][0] - pn0;
        const float pr1 = spj[pt][s][1] - pn1;
        const float pr2 = spj[pt][s][2] - pn2;
        float t0 = fmaf(pr2, wp1[6], fmaf(pr1, wp1[3], fmaf(pr0, wp1[0], bp1v[0])));
        float t1 = fmaf(pr2, wp1[7], fmaf(pr1, wp1[4], fmaf(pr0, wp1[1], bp1v[1])));
        float t2 = fmaf(pr2, wp1[8], fmaf(pr1, wp1[5], fmaf(pr0, wp1[2], bp1v[2])));
        const float mp  = (t0 + t1 + t2) * (1.f / 3.f);
        const float e0 = t0 - mp, e1 = t1 - mp, e2 = t2 - mp;
        const float vp  = (e0 * e0 + e1 * e1 + e2 * e2) * (1.f / 3.f);
        const float ivp = rsqrtf(vp + EPSLN);
        const float a0 = fmaxf(fmaf(e0 * ivp, gpv[0], bepv[0]), 0.f);
        const float a1 = fmaxf(fmaf(e1 * ivp, gpv[1], bepv[1]), 0.f);
        const float a2 = fmaxf(fmaf(e2 * ivp, gpv[2], bepv[2]), 0.f);
        if (lane == 0) { sa3[pt][s][0] = a0; sa3[pt][s][1] = a1; sa3[pt][s][2] = a2; }

        // pe for my 4 channels
        float4 pe;
        pe.x = fmaf(a0, wp2c0.x, fmaf(a1, wp2c1.x, fmaf(a2, wp2c2.x, bp24.x)));
        pe.y = fmaf(a0, wp2c0.y, fmaf(a1, wp2c1.y, fmaf(a2, wp2c2.y, bp24.y)));
        pe.z = fmaf(a0, wp2c0.z, fmaf(a1, wp2c1.z, fmaf(a2, wp2c2.z, bp24.z)));
        pe.w = fmaf(a0, wp2c0.w, fmaf(a1, wp2c1.w, fmaf(a2, wp2c2.w, bp24.w)));

        // r = kg + pe - xq
        float4 r;
        r.x = kg.x + pe.x - xq4.x;
        r.y = kg.y + pe.y - xq4.y;
        r.z = kg.z + pe.z - xq4.z;
        r.w = kg.w + pe.w - xq4.w;
        kg = kgn;

        // LayerNorm over D=16 (4-lane group)
        float sm = r.x + r.y + r.z + r.w;
        sm += __shfl_xor_sync(FULL, sm, 1, 4);
        sm += __shfl_xor_sync(FULL, sm, 2, 4);
        const float mean = sm * (1.f / 16.f);
        const float dx = r.x - mean, dy = r.y - mean, dz = r.z - mean, dw = r.w - mean;
        float vs = dx * dx + dy * dy + dz * dz + dw * dw;
        vs += __shfl_xor_sync(FULL, vs, 1, 4);
        vs += __shfl_xor_sync(FULL, vs, 2, 4);
        const float inv = rsqrtf(vs * (1.f / 16.f) + EPSLN);

        float4 a;
        a.x = fmaxf(fmaf(dx * inv, g14.x, be14.x), 0.f);
        a.y = fmaxf(fmaf(dy * inv, g14.y, be14.y), 0.f);
        a.z = fmaxf(fmaf(dz * inv, g14.z, be14.z), 0.f);
        a.w = fmaxf(fmaf(dw * inv, g14.w, be14.w), 0.f);

        // matvec 1: w[os4..os4+3] = a(16) @ Ww1[16][16]
        float4 w = b14;
#pragma unroll
        for (int q = 0; q < 4; q++) {
            const float q0 = __shfl_sync(FULL, a.x, q, 4);
            const float q1 = __shfl_sync(FULL, a.y, q, 4);
            const float q2 = __shfl_sync(FULL, a.z, q, 4);
            const float q3 = __shfl_sync(FULL, a.w, q, 4);
            const float4 r0 = *(const float4*)&sWw1[q * 4 + 0][d4];
            const float4 r1 = *(const float4*)&sWw1[q * 4 + 1][d4];
            const float4 r2 = *(const float4*)&sWw1[q * 4 + 2][d4];
            const float4 r3 = *(const float4*)&sWw1[q * 4 + 3][d4];
            w.x = fmaf(q0, r0.x, fmaf(q1, r1.x, fmaf(q2, r2.x, fmaf(q3, r3.x, w.x))));
            w.y = fmaf(q0, r0.y, fmaf(q1, r1.y, fmaf(q2, r2.y, fmaf(q3, r3.y, w.y))));
            w.z = fmaf(q0, r0.z, fmaf(q1, r1.z, fmaf(q2, r2.z, fmaf(q3, r3.z, w.z))));
            w.w = fmaf(q0, r0.w, fmaf(q1, r1.w, fmaf(q2, r2.w, fmaf(q3, r3.w, w.w))));
        }

        // LayerNorm over OS=16 + relu
        float sm2 = w.x + w.y + w.z + w.w;
        sm2 += __shfl_xor_sync(FULL, sm2, 1, 4);
        sm2 += __shfl_xor_sync(FULL, sm2, 2, 4);
        const float mean2 = sm2 * (1.f / 16.f);
        const float fx = w.x - mean2, fy = w.y - mean2, fz = w.z - mean2, fw = w.w - mean2;
        float vs2 = fx * fx + fy * fy + fz * fz + fw * fw;
        vs2 += __shfl_xor_sync(FULL, vs2, 1, 4);
        vs2 += __shfl_xor_sync(FULL, vs2, 2, 4);
        const float inv2 = rsqrtf(vs2 * (1.f / 16.f) + EPSLN);

        float4 a2v;
        a2v.x = fmaxf(fmaf(fx * inv2, g24.x, be24.x), 0.f);
        a2v.y = fmaxf(fmaf(fy * inv2, g24.y, be24.y), 0.f);
        a2v.z = fmaxf(fmaf(fz * inv2, g24.z, be24.z), 0.f);
        a2v.w = fmaxf(fmaf(fw * inv2, g24.w, be24.w), 0.f);

        // matvec 2
        float4 w2 = b24;
#pragma unroll
        for (int q = 0; q < 4; q++) {
            const float q0 = __shfl_sync(FULL, a2v.x, q, 4);
            const float q1 = __shfl_sync(FULL, a2v.y, q, 4);
            const float q2 = __shfl_sync(FULL, a2v.z, q, 4);
            const float q3 = __shfl_sync(FULL, a2v.w, q, 4);
            const float4 r0 = *(const float4*)&sWw2[q * 4 + 0][d4];
            const float4 r1 = *(const float4*)&sWw2[q * 4 + 1][d4];
            const float4 r2 = *(const float4*)&sWw2[q * 4 + 2][d4];
            const float4 r3 = *(const float4*)&sWw2[q * 4 + 3][d4];
            w2.x = fmaf(q0, r0.x, fmaf(q1, r1.x, fmaf(q2, r2.x, fmaf(q3, r3.x, w2.x))));
            w2.y = fmaf(q0, r0.y, fmaf(q1, r1.y, fmaf(q2, r2.y, fmaf(q3, r3.y, w2.y))));
            w2.z = fmaf(q0, r0.z, fmaf(q1, r1.z, fmaf(q2, r2.z, fmaf(q3, r3.z, w2.z))));
            w2.w = fmaf(q0, r0.w, fmaf(q1, r1.w, fmaf(q2, r2.w, fmaf(q3, r3.w, w2.w))));
        }

        // mean over OS=16 -> logit(s, head)
        float mm = w2.x + w2.y + w2.z + w2.w;
        mm += __shfl_xor_sync(FULL, mm, 1, 4);
        mm += __shfl_xor_sync(FULL, mm, 2, 4);
        if ((lane & 3) == 0) slog[pt][s][hh] = mm * (1.f / 16.f);
    }
    __syncwarp();

    // ---- softmax over S (per head, redundant across the 4 lanes) ----
    float mx = -1e30f;
#pragma unroll 1
    for (int s = 0; s < SDIM; s++) mx = fmaxf(mx, slog[pt][s][hh]);
    float se = 0.f;
#pragma unroll 1
    for (int s = 0; s < SDIM; s++) {
        const float e = __expf(slog[pt][s][hh] - mx);
        se += e;
        if ((lane & 3) == 0) slog[pt][s][hh] = e;
    }
    const float rse = 1.f / se;
    __syncwarp();

    // ---- pass 2: out = sum_s (v_g + pe) * w  ;  pe-part via A = sum_s w_s * a3_s
    float4 acc = make_float4(0.f, 0.f, 0.f, 0.f);
    float A0 = 0.f, A1 = 0.f, A2 = 0.f;
#pragma unroll 1
    for (int s = 0; s < SDIM; s++) {
        const float wg = slog[pt][s][hh] * rse;
        const int j = sidx[pt][s];
        const float4 vg = *(const float4*)(g_v + (size_t)j * CDIM + ch4);
        acc.x = fmaf(vg.x, wg, acc.x);
        acc.y = fmaf(vg.y, wg, acc.y);
        acc.z = fmaf(vg.z, wg, acc.z);
        acc.w = fmaf(vg.w, wg, acc.w);
        A0 = fmaf(sa3[pt][s][0], wg, A0);
        A1 = fmaf(sa3[pt][s][1], wg, A1);
        A2 = fmaf(sa3[pt][s][2], wg, A2);
    }
    // sum_s w_s = 1  =>  pe contribution = A @ Wp2 + bp2
    float4 o;
    o.x = acc.x + fmaf(A0, wp2c0.x, fmaf(A1, wp2c1.x, fmaf(A2, wp2c2.x, bp24.x)));
    o.y = acc.y + fmaf(A0, wp2c0.y, fmaf(A1, wp2c1.y, fmaf(A2, wp2c2.y, bp24.y)));
    o.z = acc.z + fmaf(A0, wp2c0.z, fmaf(A1, wp2c1.z, fmaf(A2, wp2c2.z, bp24.z)));
    o.w = acc.w + fmaf(A0, wp2c0.w, fmaf(A1, wp2c1.w, fmaf(A2, wp2c2.w, bp24.w)));
    *(float4*)(out + (size_t)n * CDIM + ch4) = o;
}

// ---------------------------------------------------------------------------
extern "C" void kernel_launch(void* const* d_in, const int* in_sizes, int n_in,
                              void* d_out, int out_size)
{
    const float* p      = (const float*)d_in[0];
    const float* x      = (const float*)d_in[1];
    const int*   idx    = (const int*)  d_in[2];
    const float* Wq     = (const float*)d_in[3];
    const float* bq     = (const float*)d_in[4];
    const float* Wk     = (const float*)d_in[5];
    const float* bk     = (const float*)d_in[6];
    const float* Wv     = (const float*)d_in[7];
    const float* bv     = (const float*)d_in[8];
    const float* Wp1    = (const float*)d_in[9];
    const float* bp1    = (const float*)d_in[10];
    const float* gp     = (const float*)d_in[11];
    const float* betap  = (const float*)d_in[12];
    const float* Wp2    = (const float*)d_in[13];
    const float* bp2    = (const float*)d_in[14];
    const float* gw1    = (const float*)d_in[15];
    const float* betaw1 = (const float*)d_in[16];
    const float* Ww1    = (const float*)d_in[17];
    const float* bw1    = (const float*)d_in[18];
    const float* gw2    = (const float*)d_in[19];
    const float* betaw2 = (const float*)d_in[20];
    const float* Ww2    = (const float*)d_in[21];
    const float* bw2    = (const float*)d_in[22];
    float* out = (float*)d_out;

    dim3 gg((NPTS + 31) / 32, 3);
    qkv_gemm<<<gg, 256>>>(x, Wq, bq, Wk, bk, Wv, bv);

    pt_fused<<<NPTS / 8, 256>>>(p, idx,
                                Wp1, bp1, gp, betap, Wp2, bp2,
                                gw1, betaw1, Ww1, bw1,
                                gw2, betaw2, Ww2, bw2, out);
}

// round 2
// speedup vs baseline: 1.3259x; 1.3259x over previous
#include <cuda_runtime.h>
#include <math.h>

// Problem constants
#define NPTS   30000
#define CDIM   128
#define SDIM   16      // neighbors
#define HDIM   8       // heads
#define DDIM   16      // dims per head
#define OSDIM  16      // O / SHARE
#define EPSLN  1e-5f

// Scratch for q,k,v (no cudaMalloc allowed)
__device__ float g_q[NPTS * CDIM];
__device__ float g_k[NPTS * CDIM];
__device__ float g_v[NPTS * CDIM];

// ---------------------------------------------------------------------------
// QKV GEMM: out = x @ W + b   (30000x128 @ 128x128), three matrices via grid.y
// ---------------------------------------------------------------------------
__global__ __launch_bounds__(256) void qkv_gemm(
    const float* __restrict__ x,
    const float* __restrict__ Wq, const float* __restrict__ bq,
    const float* __restrict__ Wk, const float* __restrict__ bk,
    const float* __restrict__ Wv, const float* __restrict__ bv)
{
    const int which = blockIdx.y;
    const float* __restrict__ W    = (which == 0) ? Wq : (which == 1) ? Wk : Wv;
    const float* __restrict__ bias = (which == 0) ? bq : (which == 1) ? bk : bv;
    float* __restrict__ out        = (which == 0) ? g_q : (which == 1) ? g_k : g_v;

    __shared__ float sx[32][128];

    const int tid  = threadIdx.x;
    const int col  = tid & 127;
    const int rh   = tid >> 7;          // 0 or 1
    const int row0 = blockIdx.x * 32;

    {
        const float4* xg  = (const float4*)(x + (size_t)row0 * CDIM);
        float4*       sx4 = (float4*)&sx[0][0];
        const int rows_valid = min(32, NPTS - row0);
        const int maxv = rows_valid * 32;
        for (int i = tid; i < 1024; i += 256)
            sx4[i] = (i < maxv) ? xg[i] : make_float4(0.f, 0.f, 0.f, 0.f);
    }
    __syncthreads();

    float acc[16];
#pragma unroll
    for (int r = 0; r < 16; r++) acc[r] = 0.f;

    const int rbase = rh * 16;
    for (int k = 0; k < 128; k += 4) {
        const float w0 = W[(k + 0) * 128 + col];
        const float w1 = W[(k + 1) * 128 + col];
        const float w2 = W[(k + 2) * 128 + col];
        const float w3 = W[(k + 3) * 128 + col];
#pragma unroll
        for (int r = 0; r < 16; r++) {
            const float4 xv = *(const float4*)&sx[rbase + r][k];
            acc[r] = fmaf(xv.x, w0, acc[r]);
            acc[r] = fmaf(xv.y, w1, acc[r]);
            acc[r] = fmaf(xv.z, w2, acc[r]);
            acc[r] = fmaf(xv.w, w3, acc[r]);
        }
    }

    const float b = bias[col];
#pragma unroll
    for (int r = 0; r < 16; r++) {
        const int n = row0 + rbase + r;
        if (n < NPTS) out[(size_t)n * CDIM + col] = acc[r] + b;
    }
}

// ---------------------------------------------------------------------------
// Fused point-transformer kernel, s-pair batched.
// One warp per point; lane owns 4 channels; 4-lane quad = one head (16 ch).
// Block = 256 thr = 8 points.
// ---------------------------------------------------------------------------
__global__ __launch_bounds__(256, 2) void pt_fused(
    const float* __restrict__ p,
    const int*   __restrict__ idx,
    const float* __restrict__ Wp1, const float* __restrict__ bp1,
    const float* __restrict__ gp,  const float* __restrict__ betap,
    const float* __restrict__ Wp2, const float* __restrict__ bp2,
    const float* __restrict__ gw1, const float* __restrict__ betaw1,
    const float* __restrict__ Ww1, const float* __restrict__ bw1,
    const float* __restrict__ gw2, const float* __restrict__ betaw2,
    const float* __restrict__ Ww2, const float* __restrict__ bw2,
    float* __restrict__ out)
{
    __shared__ float sWw1[16][16];
    __shared__ float sWw2[16][16];
    __shared__ int   sidx[8][SDIM];
    __shared__ float spj [8][SDIM][3];
    __shared__ float sa3 [8][SDIM][3];
    __shared__ float slog[8][SDIM][HDIM];
    // activation exchange buffer: [pt][s&1][head][16 + pad4] (stride 20 floats = 80B,
    // 16B-aligned, conflict-free across 8 heads)
    __shared__ float sa  [8][2][HDIM][20];

    const int tid  = threadIdx.x;
    const int pt   = tid >> 5;
    const int lane = tid & 31;
    const int n    = blockIdx.x * 8 + pt;
    const int ch4  = lane * 4;                 // first of 4 channels
    const int d4   = (lane & 3) * 4;           // position within head
    const int hh   = lane >> 2;                // head index
    const unsigned FULL = 0xffffffffu;

    // ---- cooperative loads ----
    {
        float* w1f = &sWw1[0][0];
        float* w2f = &sWw2[0][0];
        w1f[tid] = Ww1[tid];
        w2f[tid] = Ww2[tid];
    }
    if (lane < SDIM) sidx[pt][lane] = idx[n * SDIM + lane];
    __syncwarp();
    for (int t = lane; t < SDIM * 3; t += 32) {
        const int s = t / 3, c = t - 3 * s;
        spj[pt][s][c] = p[(size_t)sidx[pt][s] * 3 + c];
    }
    __syncthreads();

    // ---- per-thread hoisted parameters ----
    const float pn0 = p[n * 3 + 0], pn1 = p[n * 3 + 1], pn2 = p[n * 3 + 2];
    float wp1[9], bp1v[3], gpv[3], bepv[3];
#pragma unroll
    for (int i = 0; i < 9; i++) wp1[i] = Wp1[i];
#pragma unroll
    for (int i = 0; i < 3; i++) { bp1v[i] = bp1[i]; gpv[i] = gp[i]; bepv[i] = betap[i]; }

    const float4 xq4   = *(const float4*)(g_q + (size_t)n * CDIM + ch4);
    const float4 wp2c0 = *(const float4*)(Wp2 + 0 * CDIM + ch4);
    const float4 wp2c1 = *(const float4*)(Wp2 + 1 * CDIM + ch4);
    const float4 wp2c2 = *(const float4*)(Wp2 + 2 * CDIM + ch4);
    const float4 bp24  = *(const float4*)(bp2 + ch4);
    const float4 g14   = *(const float4*)(gw1    + d4);
    const float4 be14  = *(const float4*)(betaw1 + d4);
    const float4 b14   = *(const float4*)(bw1    + d4);
    const float4 g24   = *(const float4*)(gw2    + d4);
    const float4 be24  = *(const float4*)(betaw2 + d4);
    const float4 b24   = *(const float4*)(bw2    + d4);

    // ---- pass 1: logits + a3, two neighbors per iteration ----
    float4 kgA = *(const float4*)(g_k + (size_t)sidx[pt][0] * CDIM + ch4);
    float4 kgB = *(const float4*)(g_k + (size_t)sidx[pt][1] * CDIM + ch4);

#pragma unroll 1
    for (int s = 0; s < SDIM; s += 2) {
        // prefetch next pair
        float4 kgA2, kgB2;
        if (s < SDIM - 2) {
            kgA2 = *(const float4*)(g_k + (size_t)sidx[pt][s + 2] * CDIM + ch4);
            kgB2 = *(const float4*)(g_k + (size_t)sidx[pt][s + 3] * CDIM + ch4);
        }

        // --- positional branch for both neighbors (redundant per lane) ---
        float4 r0, r1;
#pragma unroll
        for (int u = 0; u < 2; u++) {
            const int ss = s + u;
            const float pr0 = spj[pt][ss][0] - pn0;
            const float pr1 = spj[pt][ss][1] - pn1;
            const float pr2 = spj[pt][ss][2] - pn2;
            float t0 = fmaf(pr2, wp1[6], fmaf(pr1, wp1[3], fmaf(pr0, wp1[0], bp1v[0])));
            float t1 = fmaf(pr2, wp1[7], fmaf(pr1, wp1[4], fmaf(pr0, wp1[1], bp1v[1])));
            float t2 = fmaf(pr2, wp1[8], fmaf(pr1, wp1[5], fmaf(pr0, wp1[2], bp1v[2])));
            const float mp  = (t0 + t1 + t2) * (1.f / 3.f);
            const float e0 = t0 - mp, e1 = t1 - mp, e2 = t2 - mp;
            const float vp  = (e0 * e0 + e1 * e1 + e2 * e2) * (1.f / 3.f);
            const float ivp = rsqrtf(vp + EPSLN);
            const float a0 = fmaxf(fmaf(e0 * ivp, gpv[0], bepv[0]), 0.f);
            const float a1 = fmaxf(fmaf(e1 * ivp, gpv[1], bepv[1]), 0.f);
            const float a2 = fmaxf(fmaf(e2 * ivp, gpv[2], bepv[2]), 0.f);
            if (lane == 0) { sa3[pt][ss][0] = a0; sa3[pt][ss][1] = a1; sa3[pt][ss][2] = a2; }

            float4 pe;
            pe.x = fmaf(a0, wp2c0.x, fmaf(a1, wp2c1.x, fmaf(a2, wp2c2.x, bp24.x)));
            pe.y = fmaf(a0, wp2c0.y, fmaf(a1, wp2c1.y, fmaf(a2, wp2c2.y, bp24.y)));
            pe.z = fmaf(a0, wp2c0.z, fmaf(a1, wp2c1.z, fmaf(a2, wp2c2.z, bp24.z)));
            pe.w = fmaf(a0, wp2c0.w, fmaf(a1, wp2c1.w, fmaf(a2, wp2c2.w, bp24.w)));

            const float4 kg = (u == 0) ? kgA : kgB;
            float4 r;
            r.x = kg.x + pe.x - xq4.x;
            r.y = kg.y + pe.y - xq4.y;
            r.z = kg.z + pe.z - xq4.z;
            r.w = kg.w + pe.w - xq4.w;
            if (u == 0) r0 = r; else r1 = r;
        }
        kgA = kgA2; kgB = kgB2;

        // --- LayerNorm over D=16 for both tokens (interleaved shuffles) ---
        float sm0 = r0.x + r0.y + r0.z + r0.w;
        float sm1 = r1.x + r1.y + r1.z + r1.w;
        sm0 += __shfl_xor_sync(FULL, sm0, 1, 4);
        sm1 += __shfl_xor_sync(FULL, sm1, 1, 4);
        sm0 += __shfl_xor_sync(FULL, sm0, 2, 4);
        sm1 += __shfl_xor_sync(FULL, sm1, 2, 4);
        const float mean0 = sm0 * (1.f / 16.f);
        const float mean1 = sm1 * (1.f / 16.f);
        r0.x -= mean0; r0.y -= mean0; r0.z -= mean0; r0.w -= mean0;
        r1.x -= mean1; r1.y -= mean1; r1.z -= mean1; r1.w -= mean1;
        float vs0 = r0.x * r0.x + r0.y * r0.y + r0.z * r0.z + r0.w * r0.w;
        float vs1 = r1.x * r1.x + r1.y * r1.y + r1.z * r1.z + r1.w * r1.w;
        vs0 += __shfl_xor_sync(FULL, vs0, 1, 4);
        vs1 += __shfl_xor_sync(FULL, vs1, 1, 4);
        vs0 += __shfl_xor_sync(FULL, vs0, 2, 4);
        vs1 += __shfl_xor_sync(FULL, vs1, 2, 4);
        const float inv0 = rsqrtf(vs0 * (1.f / 16.f) + EPSLN);
        const float inv1 = rsqrtf(vs1 * (1.f / 16.f) + EPSLN);

        float4 a0v, a1v;
        a0v.x = fmaxf(fmaf(r0.x * inv0, g14.x, be14.x), 0.f);
        a0v.y = fmaxf(fmaf(r0.y * inv0, g14.y, be14.y), 0.f);
        a0v.z = fmaxf(fmaf(r0.z * inv0, g14.z, be14.z), 0.f);
        a0v.w = fmaxf(fmaf(r0.w * inv0, g14.w, be14.w), 0.f);
        a1v.x = fmaxf(fmaf(r1.x * inv1, g14.x, be14.x), 0.f);
        a1v.y = fmaxf(fmaf(r1.y * inv1, g14.y, be14.y), 0.f);
        a1v.z = fmaxf(fmaf(r1.z * inv1, g14.z, be14.z), 0.f);
        a1v.w = fmaxf(fmaf(r1.w * inv1, g14.w, be14.w), 0.f);

        // --- matvec 1 via smem quad-exchange, weights shared across the pair ---
        *(float4*)&sa[pt][0][hh][d4] = a0v;
        *(float4*)&sa[pt][1][hh][d4] = a1v;
        __syncwarp();
        float4 w0 = b14, w1 = b14;
#pragma unroll
        for (int q = 0; q < 4; q++) {
            const float4 av0 = *(const float4*)&sa[pt][0][hh][q * 4];
            const float4 av1 = *(const float4*)&sa[pt][1][hh][q * 4];
            const float4 c0 = *(const float4*)&sWw1[q * 4 + 0][d4];
            const float4 c1 = *(const float4*)&sWw1[q * 4 + 1][d4];
            const float4 c2 = *(const float4*)&sWw1[q * 4 + 2][d4];
            const float4 c3 = *(const float4*)&sWw1[q * 4 + 3][d4];
            w0.x = fmaf(av0.x, c0.x, fmaf(av0.y, c1.x, fmaf(av0.z, c2.x, fmaf(av0.w, c3.x, w0.x))));
            w0.y = fmaf(av0.x, c0.y, fmaf(av0.y, c1.y, fmaf(av0.z, c2.y, fmaf(av0.w, c3.y, w0.y))));
            w0.z = fmaf(av0.x, c0.z, fmaf(av0.y, c1.z, fmaf(av0.z, c2.z, fmaf(av0.w, c3.z, w0.z))));
            w0.w = fmaf(av0.x, c0.w, fmaf(av0.y, c1.w, fmaf(av0.z, c2.w, fmaf(av0.w, c3.w, w0.w))));
            w1.x = fmaf(av1.x, c0.x, fmaf(av1.y, c1.x, fmaf(av1.z, c2.x, fmaf(av1.w, c3.x, w1.x))));
            w1.y = fmaf(av1.x, c0.y, fmaf(av1.y, c1.y, fmaf(av1.z, c2.y, fmaf(av1.w, c3.y, w1.y))));
            w1.z = fmaf(av1.x, c0.z, fmaf(av1.y, c1.z, fmaf(av1.z, c2.z, fmaf(av1.w, c3.z, w1.z))));
            w1.w = fmaf(av1.x, c0.w, fmaf(av1.y, c1.w, fmaf(av1.z, c2.w, fmaf(av1.w, c3.w, w1.w))));
        }
        __syncwarp();

        // --- LayerNorm over OS=16 + relu, both tokens ---
        float t0 = w0.x + w0.y + w0.z + w0.w;
        float t1 = w1.x + w1.y + w1.z + w1.w;
        t0 += __shfl_xor_sync(FULL, t0, 1, 4);
        t1 += __shfl_xor_sync(FULL, t1, 1, 4);
        t0 += __shfl_xor_sync(FULL, t0, 2, 4);
        t1 += __shfl_xor_sync(FULL, t1, 2, 4);
        const float m20 = t0 * (1.f / 16.f);
        const float m21 = t1 * (1.f / 16.f);
        w0.x -= m20; w0.y -= m20; w0.z -= m20; w0.w -= m20;
        w1.x -= m21; w1.y -= m21; w1.z -= m21; w1.w -= m21;
        float u0 = w0.x * w0.x + w0.y * w0.y + w0.z * w0.z + w0.w * w0.w;
        float u1 = w1.x * w1.x + w1.y * w1.y + w1.z * w1.z + w1.w * w1.w;
        u0 += __shfl_xor_sync(FULL, u0, 1, 4);
        u1 += __shfl_xor_sync(FULL, u1, 1, 4);
        u0 += __shfl_xor_sync(FULL, u0, 2, 4);
        u1 += __shfl_xor_sync(FULL, u1, 2, 4);
        const float i20 = rsqrtf(u0 * (1.f / 16.f) + EPSLN);
        const float i21 = rsqrtf(u1 * (1.f / 16.f) + EPSLN);

        float4 e0v, e1v;
        e0v.x = fmaxf(fmaf(w0.x * i20, g24.x, be24.x), 0.f);
        e0v.y = fmaxf(fmaf(w0.y * i20, g24.y, be24.y), 0.f);
        e0v.z = fmaxf(fmaf(w0.z * i20, g24.z, be24.z), 0.f);
        e0v.w = fmaxf(fmaf(w0.w * i20, g24.w, be24.w), 0.f);
        e1v.x = fmaxf(fmaf(w1.x * i21, g24.x, be24.x), 0.f);
        e1v.y = fmaxf(fmaf(w1.y * i21, g24.y, be24.y), 0.f);
        e1v.z = fmaxf(fmaf(w1.z * i21, g24.z, be24.z), 0.f);
        e1v.w = fmaxf(fmaf(w1.w * i21, g24.w, be24.w), 0.f);

        // --- matvec 2 via smem quad-exchange ---
        *(float4*)&sa[pt][0][hh][d4] = e0v;
        *(float4*)&sa[pt][1][hh][d4] = e1v;
        __syncwarp();
        float4 z0 = b24, z1 = b24;
#pragma unroll
        for (int q = 0; q < 4; q++) {
            const float4 av0 = *(const float4*)&sa[pt][0][hh][q * 4];
            const float4 av1 = *(const float4*)&sa[pt][1][hh][q * 4];
            const float4 c0 = *(const float4*)&sWw2[q * 4 + 0][d4];
            const float4 c1 = *(const float4*)&sWw2[q * 4 + 1][d4];
            const float4 c2 = *(const float4*)&sWw2[q * 4 + 2][d4];
            const float4 c3 = *(const float4*)&sWw2[q * 4 + 3][d4];
            z0.x = fmaf(av0.x, c0.x, fmaf(av0.y, c1.x, fmaf(av0.z, c2.x, fmaf(av0.w, c3.x, z0.x))));
            z0.y = fmaf(av0.x, c0.y, fmaf(av0.y, c1.y, fmaf(av0.z, c2.y, fmaf(av0.w, c3.y, z0.y))));
            z0.z = fmaf(av0.x, c0.z, fmaf(av0.y, c1.z, fmaf(av0.z, c2.z, fmaf(av0.w, c3.z, z0.z))));
            z0.w = fmaf(av0.x, c0.w, fmaf(av0.y, c1.w, fmaf(av0.z, c2.w, fmaf(av0.w, c3.w, z0.w))));
            z1.x = fmaf(av1.x, c0.x, fmaf(av1.y, c1.x, fmaf(av1.z, c2.x, fmaf(av1.w, c3.x, z1.x))));
            z1.y = fmaf(av1.x, c0.y, fmaf(av1.y, c1.y, fmaf(av1.z, c2.y, fmaf(av1.w, c3.y, z1.y))));
            z1.z = fmaf(av1.x, c0.z, fmaf(av1.y, c1.z, fmaf(av1.z, c2.z, fmaf(av1.w, c3.z, z1.z))));
            z1.w = fmaf(av1.x, c0.w, fmaf(av1.y, c1.w, fmaf(av1.z, c2.w, fmaf(av1.w, c3.w, z1.w))));
        }
        __syncwarp();

        // --- mean over OS=16 -> logits ---
        float mm0 = z0.x + z0.y + z0.z + z0.w;
        float mm1 = z1.x + z1.y + z1.z + z1.w;
        mm0 += __shfl_xor_sync(FULL, mm0, 1, 4);
        mm1 += __shfl_xor_sync(FULL, mm1, 1, 4);
        mm0 += __shfl_xor_sync(FULL, mm0, 2, 4);
        mm1 += __shfl_xor_sync(FULL, mm1, 2, 4);
        if ((lane & 3) == 0) {
            slog[pt][s + 0][hh] = mm0 * (1.f / 16.f);
            slog[pt][s + 1][hh] = mm1 * (1.f / 16.f);
        }
    }
    __syncwarp();

    // ---- softmax over S (per head, redundant across the 4 lanes) ----
    float mx = -1e30f;
#pragma unroll
    for (int s = 0; s < SDIM; s++) mx = fmaxf(mx, slog[pt][s][hh]);
    float se = 0.f;
    float ev[SDIM];
#pragma unroll
    for (int s = 0; s < SDIM; s++) {
        ev[s] = __expf(slog[pt][s][hh] - mx);
        se += ev[s];
    }
    const float rse = 1.f / se;

    // ---- pass 2: out = sum_s (v_g + pe) * w ; pe-part via A = sum_s w_s * a3_s
    float4 acc = make_float4(0.f, 0.f, 0.f, 0.f);
    float A0 = 0.f, A1 = 0.f, A2 = 0.f;
#pragma unroll 2
    for (int s = 0; s < SDIM; s++) {
        const float wg = ev[s] * rse;
        const int j = sidx[pt][s];
        const float4 vg = *(const float4*)(g_v + (size_t)j * CDIM + ch4);
        acc.x = fmaf(vg.x, wg, acc.x);
        acc.y = fmaf(vg.y, wg, acc.y);
        acc.z = fmaf(vg.z, wg, acc.z);
        acc.w = fmaf(vg.w, wg, acc.w);
        A0 = fmaf(sa3[pt][s][0], wg, A0);
        A1 = fmaf(sa3[pt][s][1], wg, A1);
        A2 = fmaf(sa3[pt][s][2], wg, A2);
    }
    float4 o;
    o.x = acc.x + fmaf(A0, wp2c0.x, fmaf(A1, wp2c1.x, fmaf(A2, wp2c2.x, bp24.x)));
    o.y = acc.y + fmaf(A0, wp2c0.y, fmaf(A1, wp2c1.y, fmaf(A2, wp2c2.y, bp24.y)));
    o.z = acc.z + fmaf(A0, wp2c0.z, fmaf(A1, wp2c1.z, fmaf(A2, wp2c2.z, bp24.z)));
    o.w = acc.w + fmaf(A0, wp2c0.w, fmaf(A1, wp2c1.w, fmaf(A2, wp2c2.w, bp24.w)));
    *(float4*)(out + (size_t)n * CDIM + ch4) = o;
}

// ---------------------------------------------------------------------------
extern "C" void kernel_launch(void* const* d_in, const int* in_sizes, int n_in,
                              void* d_out, int out_size)
{
    const float* p      = (const float*)d_in[0];
    const float* x      = (const float*)d_in[1];
    const int*   idx    = (const int*)  d_in[2];
    const float* Wq     = (const float*)d_in[3];
    const float* bq     = (const float*)d_in[4];
    const float* Wk     = (const float*)d_in[5];
    const float* bk     = (const float*)d_in[6];
    const float* Wv     = (const float*)d_in[7];
    const float* bv     = (const float*)d_in[8];
    const float* Wp1    = (const float*)d_in[9];
    const float* bp1    = (const float*)d_in[10];
    const float* gp     = (const float*)d_in[11];
    const float* betap  = (const float*)d_in[12];
    const float* Wp2    = (const float*)d_in[13];
    const float* bp2    = (const float*)d_in[14];
    const float* gw1    = (const float*)d_in[15];
    const float* betaw1 = (const float*)d_in[16];
    const float* Ww1    = (const float*)d_in[17];
    const float* bw1    = (const float*)d_in[18];
    const float* gw2    = (const float*)d_in[19];
    const float* betaw2 = (const float*)d_in[20];
    const float* Ww2    = (const float*)d_in[21];
    const float* bw2    = (const float*)d_in[22];
    float* out = (float*)d_out;

    dim3 gg((NPTS + 31) / 32, 3);
    qkv_gemm<<<gg, 256>>>(x, Wq, bq, Wk, bk, Wv, bv);

    pt_fused<<<NPTS / 8, 256>>>(p, idx,
                                Wp1, bp1, gp, betap, Wp2, bp2,
                                gw1, betaw1, Ww1, bw1,
                                gw2, betaw2, Ww2, bw2, out);
}

// round 3
// speedup vs baseline: 1.3275x; 1.0012x over previous
#include <cuda_runtime.h>
#include <math.h>

// Problem constants
#define NPTS   30000
#define CDIM   128
#define SDIM   16      // neighbors
#define HDIM   8       // heads
#define DDIM   16      // dims per head
#define OSDIM  16      // O / SHARE
#define EPSLN  1e-5f

// Scratch for q,k,v (no cudaMalloc allowed)
__device__ float g_q[NPTS * CDIM];
__device__ float g_k[NPTS * CDIM];
__device__ float g_v[NPTS * CDIM];

// ---------------------------------------------------------------------------
// QKV GEMM: out = x @ W + b   (30000x128 @ 128x128), three matrices via grid.y
// ---------------------------------------------------------------------------
__global__ __launch_bounds__(256) void qkv_gemm(
    const float* __restrict__ x,
    const float* __restrict__ Wq, const float* __restrict__ bq,
    const float* __restrict__ Wk, const float* __restrict__ bk,
    const float* __restrict__ Wv, const float* __restrict__ bv)
{
    const int which = blockIdx.y;
    const float* __restrict__ W    = (which == 0) ? Wq : (which == 1) ? Wk : Wv;
    const float* __restrict__ bias = (which == 0) ? bq : (which == 1) ? bk : bv;
    float* __restrict__ out        = (which == 0) ? g_q : (which == 1) ? g_k : g_v;

    __shared__ float sx[32][128];

    const int tid  = threadIdx.x;
    const int col  = tid & 127;
    const int rh   = tid >> 7;          // 0 or 1
    const int row0 = blockIdx.x * 32;

    {
        const float4* xg  = (const float4*)(x + (size_t)row0 * CDIM);
        float4*       sx4 = (float4*)&sx[0][0];
        const int rows_valid = min(32, NPTS - row0);
        const int maxv = rows_valid * 32;
        for (int i = tid; i < 1024; i += 256)
            sx4[i] = (i < maxv) ? xg[i] : make_float4(0.f, 0.f, 0.f, 0.f);
    }
    __syncthreads();

    float acc[16];
#pragma unroll
    for (int r = 0; r < 16; r++) acc[r] = 0.f;

    const int rbase = rh * 16;
    for (int k = 0; k < 128; k += 4) {
        const float w0 = W[(k + 0) * 128 + col];
        const float w1 = W[(k + 1) * 128 + col];
        const float w2 = W[(k + 2) * 128 + col];
        const float w3 = W[(k + 3) * 128 + col];
#pragma unroll
        for (int r = 0; r < 16; r++) {
            const float4 xv = *(const float4*)&sx[rbase + r][k];
            acc[r] = fmaf(xv.x, w0, acc[r]);
            acc[r] = fmaf(xv.y, w1, acc[r]);
            acc[r] = fmaf(xv.z, w2, acc[r]);
            acc[r] = fmaf(xv.w, w3, acc[r]);
        }
    }

    const float b = bias[col];
#pragma unroll
    for (int r = 0; r < 16; r++) {
        const int n = row0 + rbase + r;
        if (n < NPTS) out[(size_t)n * CDIM + col] = acc[r] + b;
    }
}

// ---------------------------------------------------------------------------
// Fused point-transformer kernel, s-pair batched.
// One warp per point; lane owns 4 channels; 4-lane quad = one head (16 ch).
// Block = 256 thr = 8 points.
// ---------------------------------------------------------------------------
__global__ __launch_bounds__(256, 2) void pt_fused(
    const float* __restrict__ p,
    const int*   __restrict__ idx,
    const float* __restrict__ Wp1, const float* __restrict__ bp1,
    const float* __restrict__ gp,  const float* __restrict__ betap,
    const float* __restrict__ Wp2, const float* __restrict__ bp2,
    const float* __restrict__ gw1, const float* __restrict__ betaw1,
    const float* __restrict__ Ww1, const float* __restrict__ bw1,
    const float* __restrict__ gw2, const float* __restrict__ betaw2,
    const float* __restrict__ Ww2, const float* __restrict__ bw2,
    float* __restrict__ out)
{
    __shared__ float sWw1[16][16];
    __shared__ float sWw2[16][16];
    __shared__ int   sidx[8][SDIM];
    __shared__ float spj [8][SDIM][3];
    __shared__ float sa3 [8][SDIM][3];
    __shared__ float slog[8][SDIM][HDIM];
    // activation exchange buffer: [pt][s&1][head][16 + pad4] (stride 20 floats = 80B,
    // 16B-aligned, conflict-free across 8 heads)
    __shared__ float sa  [8][2][HDIM][20];

    const int tid  = threadIdx.x;
    const int pt   = tid >> 5;
    const int lane = tid & 31;
    const int n    = blockIdx.x * 8 + pt;
    const int ch4  = lane * 4;                 // first of 4 channels
    const int d4   = (lane & 3) * 4;           // position within head
    const int hh   = lane >> 2;                // head index
    const unsigned FULL = 0xffffffffu;

    // ---- cooperative loads ----
    {
        float* w1f = &sWw1[0][0];
        float* w2f = &sWw2[0][0];
        w1f[tid] = Ww1[tid];
        w2f[tid] = Ww2[tid];
    }
    if (lane < SDIM) sidx[pt][lane] = idx[n * SDIM + lane];
    __syncwarp();
    for (int t = lane; t < SDIM * 3; t += 32) {
        const int s = t / 3, c = t - 3 * s;
        spj[pt][s][c] = p[(size_t)sidx[pt][s] * 3 + c];
    }
    __syncthreads();

    // ---- per-thread hoisted parameters ----
    const float pn0 = p[n * 3 + 0], pn1 = p[n * 3 + 1], pn2 = p[n * 3 + 2];
    float wp1[9], bp1v[3], gpv[3], bepv[3];
#pragma unroll
    for (int i = 0; i < 9; i++) wp1[i] = Wp1[i];
#pragma unroll
    for (int i = 0; i < 3; i++) { bp1v[i] = bp1[i]; gpv[i] = gp[i]; bepv[i] = betap[i]; }

    const float4 xq4   = *(const float4*)(g_q + (size_t)n * CDIM + ch4);
    const float4 wp2c0 = *(const float4*)(Wp2 + 0 * CDIM + ch4);
    const float4 wp2c1 = *(const float4*)(Wp2 + 1 * CDIM + ch4);
    const float4 wp2c2 = *(const float4*)(Wp2 + 2 * CDIM + ch4);
    const float4 bp24  = *(const float4*)(bp2 + ch4);
    const float4 g14   = *(const float4*)(gw1    + d4);
    const float4 be14  = *(const float4*)(betaw1 + d4);
    const float4 b14   = *(const float4*)(bw1    + d4);
    const float4 g24   = *(const float4*)(gw2    + d4);
    const float4 be24  = *(const float4*)(betaw2 + d4);
    const float4 b24   = *(const float4*)(bw2    + d4);

    // ---- pass 1: logits + a3, two neighbors per iteration ----
    float4 kgA = *(const float4*)(g_k + (size_t)sidx[pt][0] * CDIM + ch4);
    float4 kgB = *(const float4*)(g_k + (size_t)sidx[pt][1] * CDIM + ch4);

#pragma unroll 1
    for (int s = 0; s < SDIM; s += 2) {
        // prefetch next pair
        float4 kgA2, kgB2;
        if (s < SDIM - 2) {
            kgA2 = *(const float4*)(g_k + (size_t)sidx[pt][s + 2] * CDIM + ch4);
            kgB2 = *(const float4*)(g_k + (size_t)sidx[pt][s + 3] * CDIM + ch4);
        }

        // --- positional branch for both neighbors (redundant per lane) ---
        float4 r0, r1;
#pragma unroll
        for (int u = 0; u < 2; u++) {
            const int ss = s + u;
            const float pr0 = spj[pt][ss][0] - pn0;
            const float pr1 = spj[pt][ss][1] - pn1;
            const float pr2 = spj[pt][ss][2] - pn2;
            float t0 = fmaf(pr2, wp1[6], fmaf(pr1, wp1[3], fmaf(pr0, wp1[0], bp1v[0])));
            float t1 = fmaf(pr2, wp1[7], fmaf(pr1, wp1[4], fmaf(pr0, wp1[1], bp1v[1])));
            float t2 = fmaf(pr2, wp1[8], fmaf(pr1, wp1[5], fmaf(pr0, wp1[2], bp1v[2])));
            const float mp  = (t0 + t1 + t2) * (1.f / 3.f);
            const float e0 = t0 - mp, e1 = t1 - mp, e2 = t2 - mp;
            const float vp  = (e0 * e0 + e1 * e1 + e2 * e2) * (1.f / 3.f);
            const float ivp = rsqrtf(vp + EPSLN);
            const float a0 = fmaxf(fmaf(e0 * ivp, gpv[0], bepv[0]), 0.f);
            const float a1 = fmaxf(fmaf(e1 * ivp, gpv[1], bepv[1]), 0.f);
            const float a2 = fmaxf(fmaf(e2 * ivp, gpv[2], bepv[2]), 0.f);
            if (lane == 0) { sa3[pt][ss][0] = a0; sa3[pt][ss][1] = a1; sa3[pt][ss][2] = a2; }

            float4 pe;
            pe.x = fmaf(a0, wp2c0.x, fmaf(a1, wp2c1.x, fmaf(a2, wp2c2.x, bp24.x)));
            pe.y = fmaf(a0, wp2c0.y, fmaf(a1, wp2c1.y, fmaf(a2, wp2c2.y, bp24.y)));
            pe.z = fmaf(a0, wp2c0.z, fmaf(a1, wp2c1.z, fmaf(a2, wp2c2.z, bp24.z)));
            pe.w = fmaf(a0, wp2c0.w, fmaf(a1, wp2c1.w, fmaf(a2, wp2c2.w, bp24.w)));

            const float4 kg = (u == 0) ? kgA : kgB;
            float4 r;
            r.x = kg.x + pe.x - xq4.x;
            r.y = kg.y + pe.y - xq4.y;
            r.z = kg.z + pe.z - xq4.z;
            r.w = kg.w + pe.w - xq4.w;
            if (u == 0) r0 = r; else r1 = r;
        }
        kgA = kgA2; kgB = kgB2;

        // --- LayerNorm over D=16 for both tokens (interleaved shuffles) ---
        float sm0 = r0.x + r0.y + r0.z + r0.w;
        float sm1 = r1.x + r1.y + r1.z + r1.w;
        sm0 += __shfl_xor_sync(FULL, sm0, 1, 4);
        sm1 += __shfl_xor_sync(FULL, sm1, 1, 4);
        sm0 += __shfl_xor_sync(FULL, sm0, 2, 4);
        sm1 += __shfl_xor_sync(FULL, sm1, 2, 4);
        const float mean0 = sm0 * (1.f / 16.f);
        const float mean1 = sm1 * (1.f / 16.f);
        r0.x -= mean0; r0.y -= mean0; r0.z -= mean0; r0.w -= mean0;
        r1.x -= mean1; r1.y -= mean1; r1.z -= mean1; r1.w -= mean1;
        float vs0 = r0.x * r0.x + r0.y * r0.y + r0.z * r0.z + r0.w * r0.w;
        float vs1 = r1.x * r1.x + r1.y * r1.y + r1.z * r1.z + r1.w * r1.w;
        vs0 += __shfl_xor_sync(FULL, vs0, 1, 4);
        vs1 += __shfl_xor_sync(FULL, vs1, 1, 4);
        vs0 += __shfl_xor_sync(FULL, vs0, 2, 4);
        vs1 += __shfl_xor_sync(FULL, vs1, 2, 4);
        const float inv0 = rsqrtf(vs0 * (1.f / 16.f) + EPSLN);
        const float inv1 = rsqrtf(vs1 * (1.f / 16.f) + EPSLN);

        float4 a0v, a1v;
        a0v.x = fmaxf(fmaf(r0.x * inv0, g14.x, be14.x), 0.f);
        a0v.y = fmaxf(fmaf(r0.y * inv0, g14.y, be14.y), 0.f);
        a0v.z = fmaxf(fmaf(r0.z * inv0, g14.z, be14.z), 0.f);
        a0v.w = fmaxf(fmaf(r0.w * inv0, g14.w, be14.w), 0.f);
        a1v.x = fmaxf(fmaf(r1.x * inv1, g14.x, be14.x), 0.f);
        a1v.y = fmaxf(fmaf(r1.y * inv1, g14.y, be14.y), 0.f);
        a1v.z = fmaxf(fmaf(r1.z * inv1, g14.z, be14.z), 0.f);
        a1v.w = fmaxf(fmaf(r1.w * inv1, g14.w, be14.w), 0.f);

        // --- matvec 1 via smem quad-exchange, weights shared across the pair ---
        *(float4*)&sa[pt][0][hh][d4] = a0v;
        *(float4*)&sa[pt][1][hh][d4] = a1v;
        __syncwarp();
        float4 w0 = b14, w1 = b14;
#pragma unroll
        for (int q = 0; q < 4; q++) {
            const float4 av0 = *(const float4*)&sa[pt][0][hh][q * 4];
            const float4 av1 = *(const float4*)&sa[pt][1][hh][q * 4];
            const float4 c0 = *(const float4*)&sWw1[q * 4 + 0][d4];
            const float4 c1 = *(const float4*)&sWw1[q * 4 + 1][d4];
            const float4 c2 = *(const float4*)&sWw1[q * 4 + 2][d4];
            const float4 c3 = *(const float4*)&sWw1[q * 4 + 3][d4];
            w0.x = fmaf(av0.x, c0.x, fmaf(av0.y, c1.x, fmaf(av0.z, c2.x, fmaf(av0.w, c3.x, w0.x))));
            w0.y = fmaf(av0.x, c0.y, fmaf(av0.y, c1.y, fmaf(av0.z, c2.y, fmaf(av0.w, c3.y, w0.y))));
            w0.z = fmaf(av0.x, c0.z, fmaf(av0.y, c1.z, fmaf(av0.z, c2.z, fmaf(av0.w, c3.z, w0.z))));
            w0.w = fmaf(av0.x, c0.w, fmaf(av0.y, c1.w, fmaf(av0.z, c2.w, fmaf(av0.w, c3.w, w0.w))));
            w1.x = fmaf(av1.x, c0.x, fmaf(av1.y, c1.x, fmaf(av1.z, c2.x, fmaf(av1.w, c3.x, w1.x))));
            w1.y = fmaf(av1.x, c0.y, fmaf(av1.y, c1.y, fmaf(av1.z, c2.y, fmaf(av1.w, c3.y, w1.y))));
            w1.z = fmaf(av1.x, c0.z, fmaf(av1.y, c1.z, fmaf(av1.z, c2.z, fmaf(av1.w, c3.z, w1.z))));
            w1.w = fmaf(av1.x, c0.w, fmaf(av1.y, c1.w, fmaf(av1.z, c2.w, fmaf(av1.w, c3.w, w1.w))));
        }
        __syncwarp();

        // --- LayerNorm over OS=16 + relu, both tokens ---
        float t0 = w0.x + w0.y + w0.z + w0.w;
        float t1 = w1.x + w1.y + w1.z + w1.w;
        t0 += __shfl_xor_sync(FULL, t0, 1, 4);
        t1 += __shfl_xor_sync(FULL, t1, 1, 4);
        t0 += __shfl_xor_sync(FULL, t0, 2, 4);
        t1 += __shfl_xor_sync(FULL, t1, 2, 4);
        const float m20 = t0 * (1.f / 16.f);
        const float m21 = t1 * (1.f / 16.f);
        w0.x -= m20; w0.y -= m20; w0.z -= m20; w0.w -= m20;
        w1.x -= m21; w1.y -= m21; w1.z -= m21; w1.w -= m21;
        float u0 = w0.x * w0.x + w0.y * w0.y + w0.z * w0.z + w0.w * w0.w;
        float u1 = w1.x * w1.x + w1.y * w1.y + w1.z * w1.z + w1.w * w1.w;
        u0 += __shfl_xor_sync(FULL, u0, 1, 4);
        u1 += __shfl_xor_sync(FULL, u1, 1, 4);
        u0 += __shfl_xor_sync(FULL, u0, 2, 4);
        u1 += __shfl_xor_sync(FULL, u1, 2, 4);
        const float i20 = rsqrtf(u0 * (1.f / 16.f) + EPSLN);
        const float i21 = rsqrtf(u1 * (1.f / 16.f) + EPSLN);

        float4 e0v, e1v;
        e0v.x = fmaxf(fmaf(w0.x * i20, g24.x, be24.x), 0.f);
        e0v.y = fmaxf(fmaf(w0.y * i20, g24.y, be24.y), 0.f);
        e0v.z = fmaxf(fmaf(w0.z * i20, g24.z, be24.z), 0.f);
        e0v.w = fmaxf(fmaf(w0.w * i20, g24.w, be24.w), 0.f);
        e1v.x = fmaxf(fmaf(w1.x * i21, g24.x, be24.x), 0.f);
        e1v.y = fmaxf(fmaf(w1.y * i21, g24.y, be24.y), 0.f);
        e1v.z = fmaxf(fmaf(w1.z * i21, g24.z, be24.z), 0.f);
        e1v.w = fmaxf(fmaf(w1.w * i21, g24.w, be24.w), 0.f);

        // --- matvec 2 via smem quad-exchange ---
        *(float4*)&sa[pt][0][hh][d4] = e0v;
        *(float4*)&sa[pt][1][hh][d4] = e1v;
        __syncwarp();
        float4 z0 = b24, z1 = b24;
#pragma unroll
        for (int q = 0; q < 4; q++) {
            const float4 av0 = *(const float4*)&sa[pt][0][hh][q * 4];
            const float4 av1 = *(const float4*)&sa[pt][1][hh][q * 4];
            const float4 c0 = *(const float4*)&sWw2[q * 4 + 0][d4];
            const float4 c1 = *(const float4*)&sWw2[q * 4 + 1][d4];
            const float4 c2 = *(const float4*)&sWw2[q * 4 + 2][d4];
            const float4 c3 = *(const float4*)&sWw2[q * 4 + 3][d4];
            z0.x = fmaf(av0.x, c0.x, fmaf(av0.y, c1.x, fmaf(av0.z, c2.x, fmaf(av0.w, c3.x, z0.x))));
            z0.y = fmaf(av0.x, c0.y, fmaf(av0.y, c1.y, fmaf(av0.z, c2.y, fmaf(av0.w, c3.y, z0.y))));
            z0.z = fmaf(av0.x, c0.z, fmaf(av0.y, c1.z, fmaf(av0.z, c2.z, fmaf(av0.w, c3.z, z0.z))));
            z0.w = fmaf(av0.x, c0.w, fmaf(av0.y, c1.w, fmaf(av0.z, c2.w, fmaf(av0.w, c3.w, z0.w))));
            z1.x = fmaf(av1.x, c0.x, fmaf(av1.y, c1.x, fmaf(av1.z, c2.x, fmaf(av1.w, c3.x, z1.x))));
            z1.y = fmaf(av1.x, c0.y, fmaf(av1.y, c1.y, fmaf(av1.z, c2.y, fmaf(av1.w, c3.y, z1.y))));
            z1.z = fmaf(av1.x, c0.z, fmaf(av1.y, c1.z, fmaf(av1.z, c2.z, fmaf(av1.w, c3.z, z1.z))));
            z1.w = fmaf(av1.x, c0.w, fmaf(av1.y, c1.w, fmaf(av1.z, c2.w, fmaf(av1.w, c3.w, z1.w))));
        }
        __syncwarp();

        // --- mean over OS=16 -> logits ---
        float mm0 = z0.x + z0.y + z0.z + z0.w;
        float mm1 = z1.x + z1.y + z1.z + z1.w;
        mm0 += __shfl_xor_sync(FULL, mm0, 1, 4);
        mm1 += __shfl_xor_sync(FULL, mm1, 1, 4);
        mm0 += __shfl_xor_sync(FULL, mm0, 2, 4);
        mm1 += __shfl_xor_sync(FULL, mm1, 2, 4);
        if ((lane & 3) == 0) {
            slog[pt][s + 0][hh] = mm0 * (1.f / 16.f);
            slog[pt][s + 1][hh] = mm1 * (1.f / 16.f);
        }
    }
    __syncwarp();

    // ---- softmax over S (per head, redundant across the 4 lanes) ----
    float mx = -1e30f;
#pragma unroll
    for (int s = 0; s < SDIM; s++) mx = fmaxf(mx, slog[pt][s][hh]);
    float se = 0.f;
    float ev[SDIM];
#pragma unroll
    for (int s = 0; s < SDIM; s++) {
        ev[s] = __expf(slog[pt][s][hh] - mx);
        se += ev[s];
    }
    const float rse = 1.f / se;

    // ---- pass 2: out = sum_s (v_g + pe) * w ; pe-part via A = sum_s w_s * a3_s
    float4 acc = make_float4(0.f, 0.f, 0.f, 0.f);
    float A0 = 0.f, A1 = 0.f, A2 = 0.f;
#pragma unroll 2
    for (int s = 0; s < SDIM; s++) {
        const float wg = ev[s] * rse;
        const int j = sidx[pt][s];
        const float4 vg = *(const float4*)(g_v + (size_t)j * CDIM + ch4);
        acc.x = fmaf(vg.x, wg, acc.x);
        acc.y = fmaf(vg.y, wg, acc.y);
        acc.z = fmaf(vg.z, wg, acc.z);
        acc.w = fmaf(vg.w, wg, acc.w);
        A0 = fmaf(sa3[pt][s][0], wg, A0);
        A1 = fmaf(sa3[pt][s][1], wg, A1);
        A2 = fmaf(sa3[pt][s][2], wg, A2);
    }
    float4 o;
    o.x = acc.x + fmaf(A0, wp2c0.x, fmaf(A1, wp2c1.x, fmaf(A2, wp2c2.x, bp24.x)));
    o.y = acc.y + fmaf(A0, wp2c0.y, fmaf(A1, wp2c1.y, fmaf(A2, wp2c2.y, bp24.y)));
    o.z = acc.z + fmaf(A0, wp2c0.z, fmaf(A1, wp2c1.z, fmaf(A2, wp2c2.z, bp24.z)));
    o.w = acc.w + fmaf(A0, wp2c0.w, fmaf(A1, wp2c1.w, fmaf(A2, wp2c2.w, bp24.w)));
    *(float4*)(out + (size_t)n * CDIM + ch4) = o;
}

// ---------------------------------------------------------------------------
extern "C" void kernel_launch(void* const* d_in, const int* in_sizes, int n_in,
                              void* d_out, int out_size)
{
    const float* p      = (const float*)d_in[0];
    const float* x      = (const float*)d_in[1];
    const int*   idx    = (const int*)  d_in[2];
    const float* Wq     = (const float*)d_in[3];
    const float* bq     = (const float*)d_in[4];
    const float* Wk     = (const float*)d_in[5];
    const float* bk     = (const float*)d_in[6];
    const float* Wv     = (const float*)d_in[7];
    const float* bv     = (const float*)d_in[8];
    const float* Wp1    = (const float*)d_in[9];
    const float* bp1    = (const float*)d_in[10];
    const float* gp     = (const float*)d_in[11];
    const float* betap  = (const float*)d_in[12];
    const float* Wp2    = (const float*)d_in[13];
    const float* bp2    = (const float*)d_in[14];
    const float* gw1    = (const float*)d_in[15];
    const float* betaw1 = (const float*)d_in[16];
    const float* Ww1    = (const float*)d_in[17];
    const float* bw1    = (const float*)d_in[18];
    const float* gw2    = (const float*)d_in[19];
    const float* betaw2 = (const float*)d_in[20];
    const float* Ww2    = (const float*)d_in[21];
    const float* bw2    = (const float*)d_in[22];
    float* out = (float*)d_out;

    dim3 gg((NPTS + 31) / 32, 3);
    qkv_gemm<<<gg, 256>>>(x, Wq, bq, Wk, bk, Wv, bv);

    pt_fused<<<NPTS / 8, 256>>>(p, idx,
                                Wp1, bp1, gp, betap, Wp2, bp2,
                                gw1, betaw1, Ww1, bw1,
                                gw2, betaw2, Ww2, bw2, out);
}

// round 4
// speedup vs baseline: 1.4929x; 1.1246x over previous
#include <cuda_runtime.h>
#include <math.h>

// Problem constants
#define NPTS   30000
#define CDIM   128
#define SDIM   16      // neighbors
#define HDIM   8       // heads
#define DDIM   16      // dims per head
#define OSDIM  16      // O / SHARE
#define EPSLN  1e-5f

// Scratch for q,k,v (no cudaMalloc allowed)
__device__ float g_q[NPTS * CDIM];
__device__ float g_k[NPTS * CDIM];
__device__ float g_v[NPTS * CDIM];

// ---------------------------------------------------------------------------
// QKV GEMM: out = x @ W + b   (30000x128 @ 128x128), three matrices via grid.y
// ---------------------------------------------------------------------------
__global__ __launch_bounds__(256) void qkv_gemm(
    const float* __restrict__ x,
    const float* __restrict__ Wq, const float* __restrict__ bq,
    const float* __restrict__ Wk, const float* __restrict__ bk,
    const float* __restrict__ Wv, const float* __restrict__ bv)
{
    const int which = blockIdx.y;
    const float* __restrict__ W    = (which == 0) ? Wq : (which == 1) ? Wk : Wv;
    const float* __restrict__ bias = (which == 0) ? bq : (which == 1) ? bk : bv;
    float* __restrict__ out        = (which == 0) ? g_q : (which == 1) ? g_k : g_v;

    __shared__ float sx[32][128];

    const int tid  = threadIdx.x;
    const int col  = tid & 127;
    const int rh   = tid >> 7;          // 0 or 1
    const int row0 = blockIdx.x * 32;

    {
        const float4* xg  = (const float4*)(x + (size_t)row0 * CDIM);
        float4*       sx4 = (float4*)&sx[0][0];
        const int rows_valid = min(32, NPTS - row0);
        const int maxv = rows_valid * 32;
        for (int i = tid; i < 1024; i += 256)
            sx4[i] = (i < maxv) ? xg[i] : make_float4(0.f, 0.f, 0.f, 0.f);
    }
    __syncthreads();

    float acc[16];
#pragma unroll
    for (int r = 0; r < 16; r++) acc[r] = 0.f;

    const int rbase = rh * 16;
    for (int k = 0; k < 128; k += 4) {
        const float w0 = W[(k + 0) * 128 + col];
        const float w1 = W[(k + 1) * 128 + col];
        const float w2 = W[(k + 2) * 128 + col];
        const float w3 = W[(k + 3) * 128 + col];
#pragma unroll
        for (int r = 0; r < 16; r++) {
            const float4 xv = *(const float4*)&sx[rbase + r][k];
            acc[r] = fmaf(xv.x, w0, acc[r]);
            acc[r] = fmaf(xv.y, w1, acc[r]);
            acc[r] = fmaf(xv.z, w2, acc[r]);
            acc[r] = fmaf(xv.w, w3, acc[r]);
        }
    }

    const float b = bias[col];
#pragma unroll
    for (int r = 0; r < 16; r++) {
        const int n = row0 + rbase + r;
        if (n < NPTS) out[(size_t)n * CDIM + col] = acc[r] + b;
    }
}

// ---------------------------------------------------------------------------
// Fused point-transformer kernel, s-pair batched.
// One warp per point; lane owns 4 channels; 4-lane quad = one head (16 ch).
// Block = 256 thr = 8 points.
// matvec2 is algebraically folded: logit = e . rowmean(Ww2) + mean(bw2).
// ---------------------------------------------------------------------------
__global__ __launch_bounds__(256, 2) void pt_fused(
    const float* __restrict__ p,
    const int*   __restrict__ idx,
    const float* __restrict__ Wp1, const float* __restrict__ bp1,
    const float* __restrict__ gp,  const float* __restrict__ betap,
    const float* __restrict__ Wp2, const float* __restrict__ bp2,
    const float* __restrict__ gw1, const float* __restrict__ betaw1,
    const float* __restrict__ Ww1, const float* __restrict__ bw1,
    const float* __restrict__ gw2, const float* __restrict__ betaw2,
    const float* __restrict__ Ww2, const float* __restrict__ bw2,
    float* __restrict__ out)
{
    __shared__ float sWw1[16][16];
    __shared__ float sWw2[16][16];
    __shared__ int   sidx[8][SDIM];
    __shared__ float spj [8][SDIM][3];
    __shared__ float sa3 [8][SDIM][3];
    __shared__ float slog[8][SDIM][HDIM];
    // activation exchange buffer: [pt][s&1][head][16 + pad4]
    __shared__ float sa  [8][2][HDIM][20];

    const int tid  = threadIdx.x;
    const int pt   = tid >> 5;
    const int lane = tid & 31;
    const int n    = blockIdx.x * 8 + pt;
    const int ch4  = lane * 4;                 // first of 4 channels
    const int d4   = (lane & 3) * 4;           // position within head
    const int hh   = lane >> 2;                // head index
    const unsigned FULL = 0xffffffffu;

    // ---- cooperative loads ----
    {
        float* w1f = &sWw1[0][0];
        float* w2f = &sWw2[0][0];
        w1f[tid] = Ww1[tid];
        w2f[tid] = Ww2[tid];
    }
    if (lane < SDIM) sidx[pt][lane] = idx[n * SDIM + lane];
    __syncwarp();
    for (int t = lane; t < SDIM * 3; t += 32) {
        const int s = t / 3, c = t - 3 * s;
        spj[pt][s][c] = p[(size_t)sidx[pt][s] * 3 + c];
    }
    __syncthreads();

    // ---- per-thread hoisted parameters ----
    const float pn0 = p[n * 3 + 0], pn1 = p[n * 3 + 1], pn2 = p[n * 3 + 2];
    float wp1[9], bp1v[3], gpv[3], bepv[3];
#pragma unroll
    for (int i = 0; i < 9; i++) wp1[i] = Wp1[i];
#pragma unroll
    for (int i = 0; i < 3; i++) { bp1v[i] = bp1[i]; gpv[i] = gp[i]; bepv[i] = betap[i]; }

    const float4 xq4   = *(const float4*)(g_q + (size_t)n * CDIM + ch4);
    const float4 wp2c0 = *(const float4*)(Wp2 + 0 * CDIM + ch4);
    const float4 wp2c1 = *(const float4*)(Wp2 + 1 * CDIM + ch4);
    const float4 wp2c2 = *(const float4*)(Wp2 + 2 * CDIM + ch4);
    const float4 bp24  = *(const float4*)(bp2 + ch4);
    const float4 g14   = *(const float4*)(gw1    + d4);
    const float4 be14  = *(const float4*)(betaw1 + d4);
    const float4 b14   = *(const float4*)(bw1    + d4);
    const float4 g24   = *(const float4*)(gw2    + d4);
    const float4 be24  = *(const float4*)(betaw2 + d4);

    // ---- fold matvec2: cm[d] = rowmean_o(Ww2[d][:]) for this lane's 4 d's;
    //      mbw2 = mean(bw2)  (logit = sum_d e[d]*cm[d] + mbw2)
    float4 cm;
    {
        float s0 = 0.f, s1 = 0.f, s2 = 0.f, s3 = 0.f;
#pragma unroll
        for (int j = 0; j < 4; j++) {
            const float4 v0 = *(const float4*)&sWw2[d4 + 0][j * 4];
            const float4 v1 = *(const float4*)&sWw2[d4 + 1][j * 4];
            const float4 v2 = *(const float4*)&sWw2[d4 + 2][j * 4];
            const float4 v3 = *(const float4*)&sWw2[d4 + 3][j * 4];
            s0 += v0.x + v0.y + v0.z + v0.w;
            s1 += v1.x + v1.y + v1.z + v1.w;
            s2 += v2.x + v2.y + v2.z + v2.w;
            s3 += v3.x + v3.y + v3.z + v3.w;
        }
        cm = make_float4(s0 * (1.f / 16.f), s1 * (1.f / 16.f),
                         s2 * (1.f / 16.f), s3 * (1.f / 16.f));
    }
    float mbw2;
    {
        const float4 b2 = *(const float4*)(bw2 + d4);
        float sb = b2.x + b2.y + b2.z + b2.w;
        sb += __shfl_xor_sync(FULL, sb, 1, 4);
        sb += __shfl_xor_sync(FULL, sb, 2, 4);
        mbw2 = sb * (1.f / 16.f);
    }

    // ---- pass 1: logits + a3, two neighbors per iteration ----
    float4 kgA = *(const float4*)(g_k + (size_t)sidx[pt][0] * CDIM + ch4);
    float4 kgB = *(const float4*)(g_k + (size_t)sidx[pt][1] * CDIM + ch4);

#pragma unroll 1
    for (int s = 0; s < SDIM; s += 2) {
        // prefetch next pair
        float4 kgA2, kgB2;
        if (s < SDIM - 2) {
            kgA2 = *(const float4*)(g_k + (size_t)sidx[pt][s + 2] * CDIM + ch4);
            kgB2 = *(const float4*)(g_k + (size_t)sidx[pt][s + 3] * CDIM + ch4);
        }

        // --- positional branch for both neighbors (redundant per lane) ---
        float4 r0, r1;
#pragma unroll
        for (int u = 0; u < 2; u++) {
            const int ss = s + u;
            const float pr0 = spj[pt][ss][0] - pn0;
            const float pr1 = spj[pt][ss][1] - pn1;
            const float pr2 = spj[pt][ss][2] - pn2;
            float t0 = fmaf(pr2, wp1[6], fmaf(pr1, wp1[3], fmaf(pr0, wp1[0], bp1v[0])));
            float t1 = fmaf(pr2, wp1[7], fmaf(pr1, wp1[4], fmaf(pr0, wp1[1], bp1v[1])));
            float t2 = fmaf(pr2, wp1[8], fmaf(pr1, wp1[5], fmaf(pr0, wp1[2], bp1v[2])));
            const float mp  = (t0 + t1 + t2) * (1.f / 3.f);
            const float e0 = t0 - mp, e1 = t1 - mp, e2 = t2 - mp;
            const float vp  = (e0 * e0 + e1 * e1 + e2 * e2) * (1.f / 3.f);
            const float ivp = rsqrtf(vp + EPSLN);
            const float a0 = fmaxf(fmaf(e0 * ivp, gpv[0], bepv[0]), 0.f);
            const float a1 = fmaxf(fmaf(e1 * ivp, gpv[1], bepv[1]), 0.f);
            const float a2 = fmaxf(fmaf(e2 * ivp, gpv[2], bepv[2]), 0.f);
            if (lane == 0) { sa3[pt][ss][0] = a0; sa3[pt][ss][1] = a1; sa3[pt][ss][2] = a2; }

            float4 pe;
            pe.x = fmaf(a0, wp2c0.x, fmaf(a1, wp2c1.x, fmaf(a2, wp2c2.x, bp24.x)));
            pe.y = fmaf(a0, wp2c0.y, fmaf(a1, wp2c1.y, fmaf(a2, wp2c2.y, bp24.y)));
            pe.z = fmaf(a0, wp2c0.z, fmaf(a1, wp2c1.z, fmaf(a2, wp2c2.z, bp24.z)));
            pe.w = fmaf(a0, wp2c0.w, fmaf(a1, wp2c1.w, fmaf(a2, wp2c2.w, bp24.w)));

            const float4 kg = (u == 0) ? kgA : kgB;
            float4 r;
            r.x = kg.x + pe.x - xq4.x;
            r.y = kg.y + pe.y - xq4.y;
            r.z = kg.z + pe.z - xq4.z;
            r.w = kg.w + pe.w - xq4.w;
            if (u == 0) r0 = r; else r1 = r;
        }
        kgA = kgA2; kgB = kgB2;

        // --- LayerNorm over D=16 for both tokens (interleaved shuffles) ---
        float sm0 = r0.x + r0.y + r0.z + r0.w;
        float sm1 = r1.x + r1.y + r1.z + r1.w;
        sm0 += __shfl_xor_sync(FULL, sm0, 1, 4);
        sm1 += __shfl_xor_sync(FULL, sm1, 1, 4);
        sm0 += __shfl_xor_sync(FULL, sm0, 2, 4);
        sm1 += __shfl_xor_sync(FULL, sm1, 2, 4);
        const float mean0 = sm0 * (1.f / 16.f);
        const float mean1 = sm1 * (1.f / 16.f);
        r0.x -= mean0; r0.y -= mean0; r0.z -= mean0; r0.w -= mean0;
        r1.x -= mean1; r1.y -= mean1; r1.z -= mean1; r1.w -= mean1;
        float vs0 = r0.x * r0.x + r0.y * r0.y + r0.z * r0.z + r0.w * r0.w;
        float vs1 = r1.x * r1.x + r1.y * r1.y + r1.z * r1.z + r1.w * r1.w;
        vs0 += __shfl_xor_sync(FULL, vs0, 1, 4);
        vs1 += __shfl_xor_sync(FULL, vs1, 1, 4);
        vs0 += __shfl_xor_sync(FULL, vs0, 2, 4);
        vs1 += __shfl_xor_sync(FULL, vs1, 2, 4);
        const float inv0 = rsqrtf(vs0 * (1.f / 16.f) + EPSLN);
        const float inv1 = rsqrtf(vs1 * (1.f / 16.f) + EPSLN);

        float4 a0v, a1v;
        a0v.x = fmaxf(fmaf(r0.x * inv0, g14.x, be14.x), 0.f);
        a0v.y = fmaxf(fmaf(r0.y * inv0, g14.y, be14.y), 0.f);
        a0v.z = fmaxf(fmaf(r0.z * inv0, g14.z, be14.z), 0.f);
        a0v.w = fmaxf(fmaf(r0.w * inv0, g14.w, be14.w), 0.f);
        a1v.x = fmaxf(fmaf(r1.x * inv1, g14.x, be14.x), 0.f);
        a1v.y = fmaxf(fmaf(r1.y * inv1, g14.y, be14.y), 0.f);
        a1v.z = fmaxf(fmaf(r1.z * inv1, g14.z, be14.z), 0.f);
        a1v.w = fmaxf(fmaf(r1.w * inv1, g14.w, be14.w), 0.f);

        // --- matvec 1 via smem quad-exchange, weights shared across the pair ---
        *(float4*)&sa[pt][0][hh][d4] = a0v;
        *(float4*)&sa[pt][1][hh][d4] = a1v;
        __syncwarp();
        float4 w0 = b14, w1 = b14;
#pragma unroll
        for (int q = 0; q < 4; q++) {
            const float4 av0 = *(const float4*)&sa[pt][0][hh][q * 4];
            const float4 av1 = *(const float4*)&sa[pt][1][hh][q * 4];
            const float4 c0 = *(const float4*)&sWw1[q * 4 + 0][d4];
            const float4 c1 = *(const float4*)&sWw1[q * 4 + 1][d4];
            const float4 c2 = *(const float4*)&sWw1[q * 4 + 2][d4];
            const float4 c3 = *(const float4*)&sWw1[q * 4 + 3][d4];
            w0.x = fmaf(av0.x, c0.x, fmaf(av0.y, c1.x, fmaf(av0.z, c2.x, fmaf(av0.w, c3.x, w0.x))));
            w0.y = fmaf(av0.x, c0.y, fmaf(av0.y, c1.y, fmaf(av0.z, c2.y, fmaf(av0.w, c3.y, w0.y))));
            w0.z = fmaf(av0.x, c0.z, fmaf(av0.y, c1.z, fmaf(av0.z, c2.z, fmaf(av0.w, c3.z, w0.z))));
            w0.w = fmaf(av0.x, c0.w, fmaf(av0.y, c1.w, fmaf(av0.z, c2.w, fmaf(av0.w, c3.w, w0.w))));
            w1.x = fmaf(av1.x, c0.x, fmaf(av1.y, c1.x, fmaf(av1.z, c2.x, fmaf(av1.w, c3.x, w1.x))));
            w1.y = fmaf(av1.x, c0.y, fmaf(av1.y, c1.y, fmaf(av1.z, c2.y, fmaf(av1.w, c3.y, w1.y))));
            w1.z = fmaf(av1.x, c0.z, fmaf(av1.y, c1.z, fmaf(av1.z, c2.z, fmaf(av1.w, c3.z, w1.z))));
            w1.w = fmaf(av1.x, c0.w, fmaf(av1.y, c1.w, fmaf(av1.z, c2.w, fmaf(av1.w, c3.w, w1.w))));
        }
        __syncwarp();

        // --- LayerNorm over OS=16 + relu, both tokens ---
        float t0 = w0.x + w0.y + w0.z + w0.w;
        float t1 = w1.x + w1.y + w1.z + w1.w;
        t0 += __shfl_xor_sync(FULL, t0, 1, 4);
        t1 += __shfl_xor_sync(FULL, t1, 1, 4);
        t0 += __shfl_xor_sync(FULL, t0, 2, 4);
        t1 += __shfl_xor_sync(FULL, t1, 2, 4);
        const float m20 = t0 * (1.f / 16.f);
        const float m21 = t1 * (1.f / 16.f);
        w0.x -= m20; w0.y -= m20; w0.z -= m20; w0.w -= m20;
        w1.x -= m21; w1.y -= m21; w1.z -= m21; w1.w -= m21;
        float u0 = w0.x * w0.x + w0.y * w0.y + w0.z * w0.z + w0.w * w0.w;
        float u1 = w1.x * w1.x + w1.y * w1.y + w1.z * w1.z + w1.w * w1.w;
        u0 += __shfl_xor_sync(FULL, u0, 1, 4);
        u1 += __shfl_xor_sync(FULL, u1, 1, 4);
        u0 += __shfl_xor_sync(FULL, u0, 2, 4);
        u1 += __shfl_xor_sync(FULL, u1, 2, 4);
        const float i20 = rsqrtf(u0 * (1.f / 16.f) + EPSLN);
        const float i21 = rsqrtf(u1 * (1.f / 16.f) + EPSLN);

        // e = relu(LN2)  then  logit = e . cm + mbw2   (matvec2 folded away)
        float l0, l1;
        {
            const float e0x = fmaxf(fmaf(w0.x * i20, g24.x, be24.x), 0.f);
            const float e0y = fmaxf(fmaf(w0.y * i20, g24.y, be24.y), 0.f);
            const float e0z = fmaxf(fmaf(w0.z * i20, g24.z, be24.z), 0.f);
            const float e0w = fmaxf(fmaf(w0.w * i20, g24.w, be24.w), 0.f);
            const float e1x = fmaxf(fmaf(w1.x * i21, g24.x, be24.x), 0.f);
            const float e1y = fmaxf(fmaf(w1.y * i21, g24.y, be24.y), 0.f);
            const float e1z = fmaxf(fmaf(w1.z * i21, g24.z, be24.z), 0.f);
            const float e1w = fmaxf(fmaf(w1.w * i21, g24.w, be24.w), 0.f);
            l0 = fmaf(e0x, cm.x, fmaf(e0y, cm.y, fmaf(e0z, cm.z, e0w * cm.w)));
            l1 = fmaf(e1x, cm.x, fmaf(e1y, cm.y, fmaf(e1z, cm.z, e1w * cm.w)));
        }
        l0 += __shfl_xor_sync(FULL, l0, 1, 4);
        l1 += __shfl_xor_sync(FULL, l1, 1, 4);
        l0 += __shfl_xor_sync(FULL, l0, 2, 4);
        l1 += __shfl_xor_sync(FULL, l1, 2, 4);
        if ((lane & 3) == 0) {
            slog[pt][s + 0][hh] = l0 + mbw2;
            slog[pt][s + 1][hh] = l1 + mbw2;
        }
    }
    __syncwarp();

    // ---- softmax over S (per head, redundant across the 4 lanes) ----
    float mx = -1e30f;
#pragma unroll
    for (int s = 0; s < SDIM; s++) mx = fmaxf(mx, slog[pt][s][hh]);
    float se = 0.f;
    float ev[SDIM];
#pragma unroll
    for (int s = 0; s < SDIM; s++) {
        ev[s] = __expf(slog[pt][s][hh] - mx);
        se += ev[s];
    }
    const float rse = 1.f / se;

    // ---- pass 2: out = sum_s (v_g + pe) * w ; pe-part via A = sum_s w_s * a3_s
    float4 acc = make_float4(0.f, 0.f, 0.f, 0.f);
    float A0 = 0.f, A1 = 0.f, A2 = 0.f;
#pragma unroll 2
    for (int s = 0; s < SDIM; s++) {
        const float wg = ev[s] * rse;
        const int j = sidx[pt][s];
        const float4 vg = *(const float4*)(g_v + (size_t)j * CDIM + ch4);
        acc.x = fmaf(vg.x, wg, acc.x);
        acc.y = fmaf(vg.y, wg, acc.y);
        acc.z = fmaf(vg.z, wg, acc.z);
        acc.w = fmaf(vg.w, wg, acc.w);
        A0 = fmaf(sa3[pt][s][0], wg, A0);
        A1 = fmaf(sa3[pt][s][1], wg, A1);
        A2 = fmaf(sa3[pt][s][2], wg, A2);
    }
    float4 o;
    o.x = acc.x + fmaf(A0, wp2c0.x, fmaf(A1, wp2c1.x, fmaf(A2, wp2c2.x, bp24.x)));
    o.y = acc.y + fmaf(A0, wp2c0.y, fmaf(A1, wp2c1.y, fmaf(A2, wp2c2.y, bp24.y)));
    o.z = acc.z + fmaf(A0, wp2c0.z, fmaf(A1, wp2c1.z, fmaf(A2, wp2c2.z, bp24.z)));
    o.w = acc.w + fmaf(A0, wp2c0.w, fmaf(A1, wp2c1.w, fmaf(A2, wp2c2.w, bp24.w)));
    *(float4*)(out + (size_t)n * CDIM + ch4) = o;
}

// ---------------------------------------------------------------------------
extern "C" void kernel_launch(void* const* d_in, const int* in_sizes, int n_in,
                              void* d_out, int out_size)
{
    const float* p      = (const float*)d_in[0];
    const float* x      = (const float*)d_in[1];
    const int*   idx    = (const int*)  d_in[2];
    const float* Wq     = (const float*)d_in[3];
    const float* bq     = (const float*)d_in[4];
    const float* Wk     = (const float*)d_in[5];
    const float* bk     = (const float*)d_in[6];
    const float* Wv     = (const float*)d_in[7];
    const float* bv     = (const float*)d_in[8];
    const float* Wp1    = (const float*)d_in[9];
    const float* bp1    = (const float*)d_in[10];
    const float* gp     = (const float*)d_in[11];
    const float* betap  = (const float*)d_in[12];
    const float* Wp2    = (const float*)d_in[13];
    const float* bp2    = (const float*)d_in[14];
    const float* gw1    = (const float*)d_in[15];
    const float* betaw1 = (const float*)d_in[16];
    const float* Ww1    = (const float*)d_in[17];
    const float* bw1    = (const float*)d_in[18];
    const float* gw2    = (const float*)d_in[19];
    const float* betaw2 = (const float*)d_in[20];
    const float* Ww2    = (const float*)d_in[21];
    const float* bw2    = (const float*)d_in[22];
    float* out = (float*)d_out;

    dim3 gg((NPTS + 31) / 32, 3);
    qkv_gemm<<<gg, 256>>>(x, Wq, bq, Wk, bk, Wv, bv);

    pt_fused<<<NPTS / 8, 256>>>(p, idx,
                                Wp1, bp1, gp, betap, Wp2, bp2,
                                gw1, betaw1, Ww1, bw1,
                                gw2, betaw2, Ww2, bw2, out);
}

// round 5
// speedup vs baseline: 1.6784x; 1.1243x over previous
#include <cuda_runtime.h>
#include <math.h>

// Problem constants
#define NPTS   30000
#define CDIM   128
#define SDIM   16      // neighbors
#define HDIM   8       // heads
#define DDIM   16      // dims per head
#define OSDIM  16      // O / SHARE
#define EPSLN  1e-5f

// Scratch (no cudaMalloc allowed)
__device__ float  g_q[NPTS * CDIM];
__device__ float  g_k[NPTS * CDIM];
__device__ float  g_v[NPTS * CDIM];
__device__ float4 g_a3[NPTS * SDIM];   // relu(ln(pr@Wp1+bp1)) per (n,s), padded

// ---------------------------------------------------------------------------
// QKV GEMM: out = x @ W + b   (30000x128 @ 128x128), three matrices via grid.y
// ---------------------------------------------------------------------------
__global__ __launch_bounds__(256) void qkv_gemm(
    const float* __restrict__ x,
    const float* __restrict__ Wq, const float* __restrict__ bq,
    const float* __restrict__ Wk, const float* __restrict__ bk,
    const float* __restrict__ Wv, const float* __restrict__ bv)
{
    const int which = blockIdx.y;
    const float* __restrict__ W    = (which == 0) ? Wq : (which == 1) ? Wk : Wv;
    const float* __restrict__ bias = (which == 0) ? bq : (which == 1) ? bk : bv;
    float* __restrict__ out        = (which == 0) ? g_q : (which == 1) ? g_k : g_v;

    __shared__ float sx[32][128];

    const int tid  = threadIdx.x;
    const int col  = tid & 127;
    const int rh   = tid >> 7;
    const int row0 = blockIdx.x * 32;

    {
        const float4* xg  = (const float4*)(x + (size_t)row0 * CDIM);
        float4*       sx4 = (float4*)&sx[0][0];
        const int rows_valid = min(32, NPTS - row0);
        const int maxv = rows_valid * 32;
        for (int i = tid; i < 1024; i += 256)
            sx4[i] = (i < maxv) ? xg[i] : make_float4(0.f, 0.f, 0.f, 0.f);
    }
    __syncthreads();

    float acc[16];
#pragma unroll
    for (int r = 0; r < 16; r++) acc[r] = 0.f;

    const int rbase = rh * 16;
    for (int k = 0; k < 128; k += 4) {
        const float w0 = W[(k + 0) * 128 + col];
        const float w1 = W[(k + 1) * 128 + col];
        const float w2 = W[(k + 2) * 128 + col];
        const float w3 = W[(k + 3) * 128 + col];
#pragma unroll
        for (int r = 0; r < 16; r++) {
            const float4 xv = *(const float4*)&sx[rbase + r][k];
            acc[r] = fmaf(xv.x, w0, acc[r]);
            acc[r] = fmaf(xv.y, w1, acc[r]);
            acc[r] = fmaf(xv.z, w2, acc[r]);
            acc[r] = fmaf(xv.w, w3, acc[r]);
        }
    }

    const float b = bias[col];
#pragma unroll
    for (int r = 0; r < 16; r++) {
        const int n = row0 + rbase + r;
        if (n < NPTS) out[(size_t)n * CDIM + col] = acc[r] + b;
    }
}

// ---------------------------------------------------------------------------
// Positional precompute: a3[n,s] = relu(ln((p[j]-p[n]) @ Wp1 + bp1, gp, betap))
// One thread per (n,s).
// ---------------------------------------------------------------------------
__global__ __launch_bounds__(256) void pe_pre(
    const float* __restrict__ p, const int* __restrict__ idx,
    const float* __restrict__ Wp1, const float* __restrict__ bp1,
    const float* __restrict__ gp,  const float* __restrict__ betap)
{
    const int t = blockIdx.x * 256 + threadIdx.x;
    if (t >= NPTS * SDIM) return;
    const int n = t >> 4;
    const int j = idx[t];

    const float pr0 = p[j * 3 + 0] - p[n * 3 + 0];
    const float pr1 = p[j * 3 + 1] - p[n * 3 + 1];
    const float pr2 = p[j * 3 + 2] - p[n * 3 + 2];

    float t0 = fmaf(pr2, Wp1[6], fmaf(pr1, Wp1[3], fmaf(pr0, Wp1[0], bp1[0])));
    float t1 = fmaf(pr2, Wp1[7], fmaf(pr1, Wp1[4], fmaf(pr0, Wp1[1], bp1[1])));
    float t2 = fmaf(pr2, Wp1[8], fmaf(pr1, Wp1[5], fmaf(pr0, Wp1[2], bp1[2])));
    const float mp  = (t0 + t1 + t2) * (1.f / 3.f);
    const float e0 = t0 - mp, e1 = t1 - mp, e2 = t2 - mp;
    const float vp  = (e0 * e0 + e1 * e1 + e2 * e2) * (1.f / 3.f);
    const float ivp = rsqrtf(vp + EPSLN);
    const float a0 = fmaxf(fmaf(e0 * ivp, gp[0], betap[0]), 0.f);
    const float a1 = fmaxf(fmaf(e1 * ivp, gp[1], betap[1]), 0.f);
    const float a2 = fmaxf(fmaf(e2 * ivp, gp[2], betap[2]), 0.f);

    g_a3[t] = make_float4(a0, a1, a2, 0.f);
}

// ---------------------------------------------------------------------------
// quad (4-lane) reduction helper
// ---------------------------------------------------------------------------
__device__ __forceinline__ float quadsum(float v) {
    v += __shfl_xor_sync(0xffffffffu, v, 1, 4);
    v += __shfl_xor_sync(0xffffffffu, v, 2, 4);
    return v;
}

// ---------------------------------------------------------------------------
// Fused point-transformer kernel, 4-token batched.
// One warp per point; lane owns 4 channels; 4-lane quad = one head (16 ch).
// Block = 256 thr = 8 points. matvec2 folded into a dot with rowmean(Ww2).
// ---------------------------------------------------------------------------
__global__ __launch_bounds__(256, 3) void pt_fused(
    const int*   __restrict__ idx,
    const float* __restrict__ Wp2, const float* __restrict__ bp2,
    const float* __restrict__ gw1, const float* __restrict__ betaw1,
    const float* __restrict__ Ww1, const float* __restrict__ bw1,
    const float* __restrict__ gw2, const float* __restrict__ betaw2,
    const float* __restrict__ Ww2, const float* __restrict__ bw2,
    float* __restrict__ out)
{
    __shared__ float sWw1[16][16];
    __shared__ float sWw2[16][16];
    __shared__ int   sidx[8][SDIM];
    __shared__ float slog[8][SDIM][HDIM];
    // activation exchange: [pt][u][head][16], physical slot = ((q + head) & 3)
    __shared__ float sa[8][4][HDIM][16];

    const int tid  = threadIdx.x;
    const int pt   = tid >> 5;
    const int lane = tid & 31;
    const int n    = blockIdx.x * 8 + pt;
    const int ch4  = lane * 4;           // first of 4 channels
    const int qq   = lane & 3;           // quad position
    const int d4   = qq * 4;             // position within head
    const int hh   = lane >> 2;          // head index
    const unsigned FULL = 0xffffffffu;

    // ---- cooperative loads ----
    {
        float* w1f = &sWw1[0][0];
        float* w2f = &sWw2[0][0];
        w1f[tid] = Ww1[tid];
        w2f[tid] = Ww2[tid];
    }
    if (lane < SDIM) sidx[pt][lane] = idx[n * SDIM + lane];
    __syncthreads();

    // ---- hoisted parameters ----
    const float4 xq4   = *(const float4*)(g_q + (size_t)n * CDIM + ch4);
    const float4 wp2c0 = *(const float4*)(Wp2 + 0 * CDIM + ch4);
    const float4 wp2c1 = *(const float4*)(Wp2 + 1 * CDIM + ch4);
    const float4 wp2c2 = *(const float4*)(Wp2 + 2 * CDIM + ch4);
    const float4 bp24  = *(const float4*)(bp2 + ch4);
    const float4 g14   = *(const float4*)(gw1    + d4);
    const float4 be14  = *(const float4*)(betaw1 + d4);
    const float4 b14   = *(const float4*)(bw1    + d4);
    const float4 g24   = *(const float4*)(gw2    + d4);
    const float4 be24  = *(const float4*)(betaw2 + d4);

    // fold matvec2: cm[d] = rowmean_o(Ww2[d][:]) for this lane's 4 d's
    float4 cm;
    {
        float s0 = 0.f, s1 = 0.f, s2 = 0.f, s3 = 0.f;
#pragma unroll
        for (int j = 0; j < 4; j++) {
            const float4 v0 = *(const float4*)&sWw2[d4 + 0][j * 4];
            const float4 v1 = *(const float4*)&sWw2[d4 + 1][j * 4];
            const float4 v2 = *(const float4*)&sWw2[d4 + 2][j * 4];
            const float4 v3 = *(const float4*)&sWw2[d4 + 3][j * 4];
            s0 += v0.x + v0.y + v0.z + v0.w;
            s1 += v1.x + v1.y + v1.z + v1.w;
            s2 += v2.x + v2.y + v2.z + v2.w;
            s3 += v3.x + v3.y + v3.z + v3.w;
        }
        cm = make_float4(s0 * (1.f / 16.f), s1 * (1.f / 16.f),
                         s2 * (1.f / 16.f), s3 * (1.f / 16.f));
    }
    float mbw2;
    {
        const float4 b2 = *(const float4*)(bw2 + d4);
        mbw2 = quadsum(b2.x + b2.y + b2.z + b2.w) * (1.f / 16.f);
    }

    const int sslot = ((qq + hh) & 3) * 4;   // swizzled physical slot for my d4

    // ---- pass 1: logits, 4 tokens per iteration ----
#pragma unroll 1
    for (int s = 0; s < SDIM; s += 4) {
        // gather k rows + a3 for 4 tokens
        float4 kg[4], a3[4];
#pragma unroll
        for (int u = 0; u < 4; u++) {
            const int j = sidx[pt][s + u];
            kg[u] = *(const float4*)(g_k + (size_t)j * CDIM + ch4);
            a3[u] = g_a3[n * SDIM + s + u];
        }

        // r = kg + pe - xq ; LN1 over D=16; act -> smem (swizzled)
        float4 av[4];
#pragma unroll
        for (int u = 0; u < 4; u++) {
            float4 r;
            r.x = kg[u].x + fmaf(a3[u].x, wp2c0.x, fmaf(a3[u].y, wp2c1.x, fmaf(a3[u].z, wp2c2.x, bp24.x))) - xq4.x;
            r.y = kg[u].y + fmaf(a3[u].x, wp2c0.y, fmaf(a3[u].y, wp2c1.y, fmaf(a3[u].z, wp2c2.y, bp24.y))) - xq4.y;
            r.z = kg[u].z + fmaf(a3[u].x, wp2c0.z, fmaf(a3[u].y, wp2c1.z, fmaf(a3[u].z, wp2c2.z, bp24.z))) - xq4.z;
            r.w = kg[u].w + fmaf(a3[u].x, wp2c0.w, fmaf(a3[u].y, wp2c1.w, fmaf(a3[u].z, wp2c2.w, bp24.w))) - xq4.w;

            const float mean = quadsum(r.x + r.y + r.z + r.w) * (1.f / 16.f);
            r.x -= mean; r.y -= mean; r.z -= mean; r.w -= mean;
            const float var = quadsum(r.x * r.x + r.y * r.y + r.z * r.z + r.w * r.w) * (1.f / 16.f);
            const float inv = rsqrtf(var + EPSLN);
            av[u].x = fmaxf(fmaf(r.x * inv, g14.x, be14.x), 0.f);
            av[u].y = fmaxf(fmaf(r.y * inv, g14.y, be14.y), 0.f);
            av[u].z = fmaxf(fmaf(r.z * inv, g14.z, be14.z), 0.f);
            av[u].w = fmaxf(fmaf(r.w * inv, g14.w, be14.w), 0.f);
        }
#pragma unroll
        for (int u = 0; u < 4; u++)
            *(float4*)&sa[pt][u][hh][sslot] = av[u];
        __syncwarp();

        // matvec1: weights shared across all 4 tokens
        float4 w[4];
#pragma unroll
        for (int u = 0; u < 4; u++) w[u] = b14;
#pragma unroll
        for (int q = 0; q < 4; q++) {
            const float4 c0 = *(const float4*)&sWw1[q * 4 + 0][d4];
            const float4 c1 = *(const float4*)&sWw1[q * 4 + 1][d4];
            const float4 c2 = *(const float4*)&sWw1[q * 4 + 2][d4];
            const float4 c3 = *(const float4*)&sWw1[q * 4 + 3][d4];
            const int ps = ((q + hh) & 3) * 4;  // physical slot of logical q
#pragma unroll
            for (int u = 0; u < 4; u++) {
                const float4 a = *(const float4*)&sa[pt][u][hh][ps];
                w[u].x = fmaf(a.x, c0.x, fmaf(a.y, c1.x, fmaf(a.z, c2.x, fmaf(a.w, c3.x, w[u].x))));
                w[u].y = fmaf(a.x, c0.y, fmaf(a.y, c1.y, fmaf(a.z, c2.y, fmaf(a.w, c3.y, w[u].y))));
                w[u].z = fmaf(a.x, c0.z, fmaf(a.y, c1.z, fmaf(a.z, c2.z, fmaf(a.w, c3.z, w[u].z))));
                w[u].w = fmaf(a.x, c0.w, fmaf(a.y, c1.w, fmaf(a.z, c2.w, fmaf(a.w, c3.w, w[u].w))));
            }
        }
        __syncwarp();

        // LN2 + relu + folded matvec2 -> logit
#pragma unroll
        for (int u = 0; u < 4; u++) {
            const float m2 = quadsum(w[u].x + w[u].y + w[u].z + w[u].w) * (1.f / 16.f);
            const float fx = w[u].x - m2, fy = w[u].y - m2, fz = w[u].z - m2, fw = w[u].w - m2;
            const float v2 = quadsum(fx * fx + fy * fy + fz * fz + fw * fw) * (1.f / 16.f);
            const float i2 = rsqrtf(v2 + EPSLN);
            const float ex = fmaxf(fmaf(fx * i2, g24.x, be24.x), 0.f);
            const float ey = fmaxf(fmaf(fy * i2, g24.y, be24.y), 0.f);
            const float ez = fmaxf(fmaf(fz * i2, g24.z, be24.z), 0.f);
            const float ew = fmaxf(fmaf(fw * i2, g24.w, be24.w), 0.f);
            const float l = quadsum(fmaf(ex, cm.x, fmaf(ey, cm.y, fmaf(ez, cm.z, ew * cm.w))));
            if (qq == 0) slog[pt][s + u][hh] = l + mbw2;
        }
    }
    __syncwarp();

    // ---- softmax over S (per head, redundant across the 4 lanes) ----
    float mx = -1e30f;
#pragma unroll
    for (int s = 0; s < SDIM; s++) mx = fmaxf(mx, slog[pt][s][hh]);
    float se = 0.f;
    float ev[SDIM];
#pragma unroll
    for (int s = 0; s < SDIM; s++) {
        ev[s] = __expf(slog[pt][s][hh] - mx);
        se += ev[s];
    }
    const float rse = 1.f / se;

    // ---- pass 2: out = sum_s (v_g + pe) * w ; pe-part via A = sum_s w_s * a3_s
    float4 acc = make_float4(0.f, 0.f, 0.f, 0.f);
    float A0 = 0.f, A1 = 0.f, A2 = 0.f;
#pragma unroll 2
    for (int s = 0; s < SDIM; s++) {
        const float wg = ev[s] * rse;
        const int j = sidx[pt][s];
        const float4 vg = *(const float4*)(g_v + (size_t)j * CDIM + ch4);
        const float4 a3 = g_a3[n * SDIM + s];
        acc.x = fmaf(vg.x, wg, acc.x);
        acc.y = fmaf(vg.y, wg, acc.y);
        acc.z = fmaf(vg.z, wg, acc.z);
        acc.w = fmaf(vg.w, wg, acc.w);
        A0 = fmaf(a3.x, wg, A0);
        A1 = fmaf(a3.y, wg, A1);
        A2 = fmaf(a3.z, wg, A2);
    }
    float4 o;
    o.x = acc.x + fmaf(A0, wp2c0.x, fmaf(A1, wp2c1.x, fmaf(A2, wp2c2.x, bp24.x)));
    o.y = acc.y + fmaf(A0, wp2c0.y, fmaf(A1, wp2c1.y, fmaf(A2, wp2c2.y, bp24.y)));
    o.z = acc.z + fmaf(A0, wp2c0.z, fmaf(A1, wp2c1.z, fmaf(A2, wp2c2.z, bp24.z)));
    o.w = acc.w + fmaf(A0, wp2c0.w, fmaf(A1, wp2c1.w, fmaf(A2, wp2c2.w, bp24.w)));
    *(float4*)(out + (size_t)n * CDIM + ch4) = o;
}

// ---------------------------------------------------------------------------
extern "C" void kernel_launch(void* const* d_in, const int* in_sizes, int n_in,
                              void* d_out, int out_size)
{
    const float* p      = (const float*)d_in[0];
    const float* x      = (const float*)d_in[1];
    const int*   idx    = (const int*)  d_in[2];
    const float* Wq     = (const float*)d_in[3];
    const float* bq     = (const float*)d_in[4];
    const float* Wk     = (const float*)d_in[5];
    const float* bk     = (const float*)d_in[6];
    const float* Wv     = (const float*)d_in[7];
    const float* bv     = (const float*)d_in[8];
    const float* Wp1    = (const float*)d_in[9];
    const float* bp1    = (const float*)d_in[10];
    const float* gp     = (const float*)d_in[11];
    const float* betap  = (const float*)d_in[12];
    const float* Wp2    = (const float*)d_in[13];
    const float* bp2    = (const float*)d_in[14];
    const float* gw1    = (const float*)d_in[15];
    const float* betaw1 = (const float*)d_in[16];
    const float* Ww1    = (const float*)d_in[17];
    const float* bw1    = (const float*)d_in[18];
    const float* gw2    = (const float*)d_in[19];
    const float* betaw2 = (const float*)d_in[20];
    const float* Ww2    = (const float*)d_in[21];
    const float* bw2    = (const float*)d_in[22];
    float* out = (float*)d_out;

    dim3 gg((NPTS + 31) / 32, 3);
    qkv_gemm<<<gg, 256>>>(x, Wq, bq, Wk, bk, Wv, bv);

    pe_pre<<<(NPTS * SDIM + 255) / 256, 256>>>(p, idx, Wp1, bp1, gp, betap);

    pt_fused<<<NPTS / 8, 256>>>(idx,
                                Wp2, bp2,
                                gw1, betaw1, Ww1, bw1,
                                gw2, betaw2, Ww2, bw2, out);
}

// round 7
// speedup vs baseline: 1.8793x; 1.1197x over previous
#include <cuda_runtime.h>
#include <math.h>

// Problem constants
#define NPTS   30000
#define CDIM   128
#define SDIM   16      // neighbors
#define HDIM   8       // heads
#define DDIM   16      // dims per head
#define OSDIM  16      // O / SHARE
#define EPSLN  1e-5f

// Scratch (no cudaMalloc allowed)
__device__ float  g_q[NPTS * CDIM];
__device__ float  g_k[NPTS * CDIM];
__device__ float  g_v[NPTS * CDIM];
__device__ float4 g_a3[NPTS * SDIM];   // relu(ln(pr@Wp1+bp1)) per (n,s), padded

// ---------------------------------------------------------------------------
// tf32 helpers
// ---------------------------------------------------------------------------
__device__ __forceinline__ unsigned tf32_rna(float v) {
    unsigned r;
    asm("cvt.rna.tf32.f32 %0, %1;" : "=r"(r) : "f"(v));
    return r;
}
// split v into hi (tf32) + lo (tf32 of residual), both returned as f32 bit patterns
__device__ __forceinline__ float2 tf32_split(float v) {
    const unsigned hb = tf32_rna(v);
    const float hf = __uint_as_float(hb);
    const unsigned lb = tf32_rna(v - hf);
    return make_float2(hf, __uint_as_float(lb));
}

__device__ __forceinline__ void mma_tf32(float* d, const unsigned* a,
                                         unsigned b0, unsigned b1) {
    asm volatile(
        "mma.sync.aligned.m16n8k8.row.col.f32.tf32.tf32.f32 "
        "{%0,%1,%2,%3}, {%4,%5,%6,%7}, {%8,%9}, {%0,%1,%2,%3};"
        : "+f"(d[0]), "+f"(d[1]), "+f"(d[2]), "+f"(d[3])
        : "r"(a[0]), "r"(a[1]), "r"(a[2]), "r"(a[3]), "r"(b0), "r"(b1));
}

// ---------------------------------------------------------------------------
// QKV GEMM via tf32 tensor cores with hi/lo fp32 emulation.
// out = x @ W + b  (30000x128 @ 128x128), three matrices via grid.y.
// Block 256 thr = 8 warps (4 M-warps x 2 N-warps), block tile 128x128,
// warp tile 32x64, K chunks of 8, double-buffered smem of pre-split (hi,lo).
// ---------------------------------------------------------------------------
__global__ __launch_bounds__(256, 2) void qkv_gemm_tc(
    const float* __restrict__ x,
    const float* __restrict__ Wq, const float* __restrict__ bq,
    const float* __restrict__ Wk, const float* __restrict__ bk,
    const float* __restrict__ Wv, const float* __restrict__ bv)
{
    const int which = blockIdx.y;
    const float* __restrict__ W    = (which == 0) ? Wq : (which == 1) ? Wk : Wv;
    const float* __restrict__ bias = (which == 0) ? bq : (which == 1) ? bk : bv;
    float* __restrict__ out        = (which == 0) ? g_q : (which == 1) ? g_k : g_v;

    __shared__ float2 sx[2][128][8];    // [stage][row][k]  (hi,lo)
    __shared__ float2 sw[2][8][132];    // [stage][k][n]    (hi,lo), padded

    const int tid    = threadIdx.x;
    const int lane   = tid & 31;
    const int wid    = tid >> 5;
    const int warp_m = wid & 3;         // 0..3  -> 32 rows each
    const int warp_n = wid >> 2;        // 0..1  -> 64 cols each
    const int row0   = blockIdx.x * 128;

    const int lg  = lane >> 2;          // group id 0..7
    const int lt  = lane & 3;           // thread-in-group 0..3

    // staging thread mapping
    const int xrow  = tid >> 1;               // 0..127
    const int xkoff = (tid & 1) * 4;          // 0 or 4
    const int wkrow = tid >> 5;               // 0..7
    const int wn4   = (tid & 31) * 4;         // 0..124

    float d[2][8][4];
#pragma unroll
    for (int g = 0; g < 2; g++)
#pragma unroll
        for (int nb = 0; nb < 8; nb++)
#pragma unroll
            for (int c = 0; c < 4; c++) d[g][nb][c] = 0.f;

    // ---- prologue: load chunk 0 into stage 0 ----
    {
        float4 xv = make_float4(0.f, 0.f, 0.f, 0.f);
        if (row0 + xrow < NPTS)
            xv = *(const float4*)(x + (size_t)(row0 + xrow) * CDIM + xkoff);
        const float4 wv = *(const float4*)(W + (size_t)wkrow * CDIM + wn4);
        sx[0][xrow][xkoff + 0] = tf32_split(xv.x);
        sx[0][xrow][xkoff + 1] = tf32_split(xv.y);
        sx[0][xrow][xkoff + 2] = tf32_split(xv.z);
        sx[0][xrow][xkoff + 3] = tf32_split(xv.w);
        sw[0][wkrow][wn4 + 0] = tf32_split(wv.x);
        sw[0][wkrow][wn4 + 1] = tf32_split(wv.y);
        sw[0][wkrow][wn4 + 2] = tf32_split(wv.z);
        sw[0][wkrow][wn4 + 3] = tf32_split(wv.w);
    }
    __syncthreads();

#pragma unroll 1
    for (int c = 0; c < 16; c++) {
        const int cur = c & 1;

        // issue next chunk's global loads early
        float4 xv, wv;
        const bool more = (c < 15);
        if (more) {
            const int k0 = (c + 1) * 8;
            xv = make_float4(0.f, 0.f, 0.f, 0.f);
            if (row0 + xrow < NPTS)
                xv = *(const float4*)(x + (size_t)(row0 + xrow) * CDIM + k0 + xkoff);
            wv = *(const float4*)(W + (size_t)(k0 + wkrow) * CDIM + wn4);
        }

        // ---- compute on stage cur ----
        // A fragments (two 16-row groups), hi & lo
        unsigned a_hi[2][4], a_lo[2][4];
#pragma unroll
        for (int g = 0; g < 2; g++) {
            const int rb = warp_m * 32 + g * 16;
            const float2 v0 = sx[cur][rb + lg    ][lt    ];
            const float2 v1 = sx[cur][rb + lg + 8][lt    ];
            const float2 v2 = sx[cur][rb + lg    ][lt + 4];
            const float2 v3 = sx[cur][rb + lg + 8][lt + 4];
            a_hi[g][0] = __float_as_uint(v0.x); a_lo[g][0] = __float_as_uint(v0.y);
            a_hi[g][1] = __float_as_uint(v1.x); a_lo[g][1] = __float_as_uint(v1.y);
            a_hi[g][2] = __float_as_uint(v2.x); a_lo[g][2] = __float_as_uint(v2.y);
            a_hi[g][3] = __float_as_uint(v3.x); a_lo[g][3] = __float_as_uint(v3.y);
        }

#pragma unroll
        for (int nb = 0; nb < 8; nb++) {
            const int ncol = warp_n * 64 + nb * 8 + lg;
            const float2 b0v = sw[cur][lt    ][ncol];
            const float2 b1v = sw[cur][lt + 4][ncol];
            const unsigned bh0 = __float_as_uint(b0v.x), bl0 = __float_as_uint(b0v.y);
            const unsigned bh1 = __float_as_uint(b1v.x), bl1 = __float_as_uint(b1v.y);
#pragma unroll
            for (int g = 0; g < 2; g++) {
                mma_tf32(d[g][nb], a_hi[g], bh0, bh1);   // hi*hi
                mma_tf32(d[g][nb], a_hi[g], bl0, bl1);   // hi*lo
                mma_tf32(d[g][nb], a_lo[g], bh0, bh1);   // lo*hi
            }
        }

        // ---- stage next chunk ----
        if (more) {
            const int nxt = cur ^ 1;
            sx[nxt][xrow][xkoff + 0] = tf32_split(xv.x);
            sx[nxt][xrow][xkoff + 1] = tf32_split(xv.y);
            sx[nxt][xrow][xkoff + 2] = tf32_split(xv.z);
            sx[nxt][xrow][xkoff + 3] = tf32_split(xv.w);
            sw[nxt][wkrow][wn4 + 0] = tf32_split(wv.x);
            sw[nxt][wkrow][wn4 + 1] = tf32_split(wv.y);
            sw[nxt][wkrow][wn4 + 2] = tf32_split(wv.z);
            sw[nxt][wkrow][wn4 + 3] = tf32_split(wv.w);
        }
        __syncthreads();
    }

    // ---- epilogue: add bias, write ----
#pragma unroll
    for (int nb = 0; nb < 8; nb++) {
        const int col = warp_n * 64 + nb * 8 + lt * 2;
        const float2 bs = *(const float2*)(bias + col);
#pragma unroll
        for (int g = 0; g < 2; g++) {
            const int rbase = row0 + warp_m * 32 + g * 16 + lg;
            if (rbase < NPTS) {
                float2 o = make_float2(d[g][nb][0] + bs.x, d[g][nb][1] + bs.y);
                *(float2*)(out + (size_t)rbase * CDIM + col) = o;
            }
            if (rbase + 8 < NPTS) {
                float2 o = make_float2(d[g][nb][2] + bs.x, d[g][nb][3] + bs.y);
                *(float2*)(out + (size_t)(rbase + 8) * CDIM + col) = o;
            }
        }
    }
}

// ---------------------------------------------------------------------------
// Positional precompute: a3[n,s] = relu(ln((p[j]-p[n]) @ Wp1 + bp1, gp, betap))
// ---------------------------------------------------------------------------
__global__ __launch_bounds__(256) void pe_pre(
    const float* __restrict__ p, const int* __restrict__ idx,
    const float* __restrict__ Wp1, const float* __restrict__ bp1,
    const float* __restrict__ gp,  const float* __restrict__ betap)
{
    const int t = blockIdx.x * 256 + threadIdx.x;
    if (t >= NPTS * SDIM) return;
    const int n = t >> 4;
    const int j = idx[t];

    const float pr0 = p[j * 3 + 0] - p[n * 3 + 0];
    const float pr1 = p[j * 3 + 1] - p[n * 3 + 1];
    const float pr2 = p[j * 3 + 2] - p[n * 3 + 2];

    float t0 = fmaf(pr2, Wp1[6], fmaf(pr1, Wp1[3], fmaf(pr0, Wp1[0], bp1[0])));
    float t1 = fmaf(pr2, Wp1[7], fmaf(pr1, Wp1[4], fmaf(pr0, Wp1[1], bp1[1])));
    float t2 = fmaf(pr2, Wp1[8], fmaf(pr1, Wp1[5], fmaf(pr0, Wp1[2], bp1[2])));
    const float mp  = (t0 + t1 + t2) * (1.f / 3.f);
    const float e0 = t0 - mp, e1 = t1 - mp, e2 = t2 - mp;
    const float vp  = (e0 * e0 + e1 * e1 + e2 * e2) * (1.f / 3.f);
    const float ivp = rsqrtf(vp + EPSLN);
    const float a0 = fmaxf(fmaf(e0 * ivp, gp[0], betap[0]), 0.f);
    const float a1 = fmaxf(fmaf(e1 * ivp, gp[1], betap[1]), 0.f);
    const float a2 = fmaxf(fmaf(e2 * ivp, gp[2], betap[2]), 0.f);

    g_a3[t] = make_float4(a0, a1, a2, 0.f);
}

// ---------------------------------------------------------------------------
// quad (4-lane) reduction helper
// ---------------------------------------------------------------------------
__device__ __forceinline__ float quadsum(float v) {
    v += __shfl_xor_sync(0xffffffffu, v, 1, 4);
    v += __shfl_xor_sync(0xffffffffu, v, 2, 4);
    return v;
}

// ---------------------------------------------------------------------------
// Fused point-transformer kernel, 4-token batched.
// One warp per point; lane owns 4 channels; 4-lane quad = one head (16 ch).
// Block = 256 thr = 8 points. matvec2 folded into a dot with rowmean(Ww2).
// ---------------------------------------------------------------------------
__global__ __launch_bounds__(256, 3) void pt_fused(
    const int*   __restrict__ idx,
    const float* __restrict__ Wp2, const float* __restrict__ bp2,
    const float* __restrict__ gw1, const float* __restrict__ betaw1,
    const float* __restrict__ Ww1, const float* __restrict__ bw1,
    const float* __restrict__ gw2, const float* __restrict__ betaw2,
    const float* __restrict__ Ww2, const float* __restrict__ bw2,
    float* __restrict__ out)
{
    __shared__ float sWw1[16][16];
    __shared__ float sWw2[16][16];
    __shared__ int   sidx[8][SDIM];
    __shared__ float slog[8][SDIM][HDIM];
    // activation exchange: [pt][u][head][16], physical slot = ((q + head) & 3)
    __shared__ float sa[8][4][HDIM][16];

    const int tid  = threadIdx.x;
    const int pt   = tid >> 5;
    const int lane = tid & 31;
    const int n    = blockIdx.x * 8 + pt;
    const int ch4  = lane * 4;           // first of 4 channels
    const int qq   = lane & 3;           // quad position
    const int d4   = qq * 4;             // position within head
    const int hh   = lane >> 2;          // head index

    // ---- cooperative loads ----
    {
        float* w1f = &sWw1[0][0];
        float* w2f = &sWw2[0][0];
        w1f[tid] = Ww1[tid];
        w2f[tid] = Ww2[tid];
    }
    if (lane < SDIM) sidx[pt][lane] = idx[n * SDIM + lane];
    __syncthreads();

    // ---- hoisted parameters ----
    const float4 xq4   = *(const float4*)(g_q + (size_t)n * CDIM + ch4);
    const float4 wp2c0 = *(const float4*)(Wp2 + 0 * CDIM + ch4);
    const float4 wp2c1 = *(const float4*)(Wp2 + 1 * CDIM + ch4);
    const float4 wp2c2 = *(const float4*)(Wp2 + 2 * CDIM + ch4);
    const float4 bp24  = *(const float4*)(bp2 + ch4);
    const float4 g14   = *(const float4*)(gw1    + d4);
    const float4 be14  = *(const float4*)(betaw1 + d4);
    const float4 b14   = *(const float4*)(bw1    + d4);
    const float4 g24   = *(const float4*)(gw2    + d4);
    const float4 be24  = *(const float4*)(betaw2 + d4);

    // fold matvec2: cm[d] = rowmean_o(Ww2[d][:]) for this lane's 4 d's
    float4 cm;
    {
        float s0 = 0.f, s1 = 0.f, s2 = 0.f, s3 = 0.f;
#pragma unroll
        for (int j = 0; j < 4; j++) {
            const float4 v0 = *(const float4*)&sWw2[d4 + 0][j * 4];
            const float4 v1 = *(const float4*)&sWw2[d4 + 1][j * 4];
            const float4 v2 = *(const float4*)&sWw2[d4 + 2][j * 4];
            const float4 v3 = *(const float4*)&sWw2[d4 + 3][j * 4];
            s0 += v0.x + v0.y + v0.z + v0.w;
            s1 += v1.x + v1.y + v1.z + v1.w;
            s2 += v2.x + v2.y + v2.z + v2.w;
            s3 += v3.x + v3.y + v3.z + v3.w;
        }
        cm = make_float4(s0 * (1.f / 16.f), s1 * (1.f / 16.f),
                         s2 * (1.f / 16.f), s3 * (1.f / 16.f));
    }
    float mbw2;
    {
        const float4 b2 = *(const float4*)(bw2 + d4);
        mbw2 = quadsum(b2.x + b2.y + b2.z + b2.w) * (1.f / 16.f);
    }

    const int sslot = ((qq + hh) & 3) * 4;   // swizzled physical slot for my d4

    // ---- pass 1: logits, 4 tokens per iteration ----
#pragma unroll 1
    for (int s = 0; s < SDIM; s += 4) {
        // gather k rows + a3 for 4 tokens
        float4 kg[4], a3[4];
#pragma unroll
        for (int u = 0; u < 4; u++) {
            const int j = sidx[pt][s + u];
            kg[u] = *(const float4*)(g_k + (size_t)j * CDIM + ch4);
            a3[u] = g_a3[n * SDIM + s + u];
        }

        // r = kg + pe - xq ; LN1 over D=16; act -> smem (swizzled)
        float4 av[4];
#pragma unroll
        for (int u = 0; u < 4; u++) {
            float4 r;
            r.x = kg[u].x + fmaf(a3[u].x, wp2c0.x, fmaf(a3[u].y, wp2c1.x, fmaf(a3[u].z, wp2c2.x, bp24.x))) - xq4.x;
            r.y = kg[u].y + fmaf(a3[u].x, wp2c0.y, fmaf(a3[u].y, wp2c1.y, fmaf(a3[u].z, wp2c2.y, bp24.y))) - xq4.y;
            r.z = kg[u].z + fmaf(a3[u].x, wp2c0.z, fmaf(a3[u].y, wp2c1.z, fmaf(a3[u].z, wp2c2.z, bp24.z))) - xq4.z;
            r.w = kg[u].w + fmaf(a3[u].x, wp2c0.w, fmaf(a3[u].y, wp2c1.w, fmaf(a3[u].z, wp2c2.w, bp24.w))) - xq4.w;

            const float mean = quadsum(r.x + r.y + r.z + r.w) * (1.f / 16.f);
            r.x -= mean; r.y -= mean; r.z -= mean; r.w -= mean;
            const float var = quadsum(r.x * r.x + r.y * r.y + r.z * r.z + r.w * r.w) * (1.f / 16.f);
            const float inv = rsqrtf(var + EPSLN);
            av[u].x = fmaxf(fmaf(r.x * inv, g14.x, be14.x), 0.f);
            av[u].y = fmaxf(fmaf(r.y * inv, g14.y, be14.y), 0.f);
            av[u].z = fmaxf(fmaf(r.z * inv, g14.z, be14.z), 0.f);
            av[u].w = fmaxf(fmaf(r.w * inv, g14.w, be14.w), 0.f);
        }
#pragma unroll
        for (int u = 0; u < 4; u++)
            *(float4*)&sa[pt][u][hh][sslot] = av[u];
        __syncwarp();

        // matvec1: weights shared across all 4 tokens
        float4 w[4];
#pragma unroll
        for (int u = 0; u < 4; u++) w[u] = b14;
#pragma unroll
        for (int q = 0; q < 4; q++) {
            const float4 c0 = *(const float4*)&sWw1[q * 4 + 0][d4];
            const float4 c1 = *(const float4*)&sWw1[q * 4 + 1][d4];
            const float4 c2 = *(const float4*)&sWw1[q * 4 + 2][d4];
            const float4 c3 = *(const float4*)&sWw1[q * 4 + 3][d4];
            const int ps = ((q + hh) & 3) * 4;  // physical slot of logical q
#pragma unroll
            for (int u = 0; u < 4; u++) {
                const float4 a = *(const float4*)&sa[pt][u][hh][ps];
                w[u].x = fmaf(a.x, c0.x, fmaf(a.y, c1.x, fmaf(a.z, c2.x, fmaf(a.w, c3.x, w[u].x))));
                w[u].y = fmaf(a.x, c0.y, fmaf(a.y, c1.y, fmaf(a.z, c2.y, fmaf(a.w, c3.y, w[u].y))));
                w[u].z = fmaf(a.x, c0.z, fmaf(a.y, c1.z, fmaf(a.z, c2.z, fmaf(a.w, c3.z, w[u].z))));
                w[u].w = fmaf(a.x, c0.w, fmaf(a.y, c1.w, fmaf(a.z, c2.w, fmaf(a.w, c3.w, w[u].w))));
            }
        }
        __syncwarp();

        // LN2 + relu + folded matvec2 -> logit
#pragma unroll
        for (int u = 0; u < 4; u++) {
            const float m2 = quadsum(w[u].x + w[u].y + w[u].z + w[u].w) * (1.f / 16.f);
            const float fx = w[u].x - m2, fy = w[u].y - m2, fz = w[u].z - m2, fw = w[u].w - m2;
            const float v2 = quadsum(fx * fx + fy * fy + fz * fz + fw * fw) * (1.f / 16.f);
            const float i2 = rsqrtf(v2 + EPSLN);
            const float ex = fmaxf(fmaf(fx * i2, g24.x, be24.x), 0.f);
            const float ey = fmaxf(fmaf(fy * i2, g24.y, be24.y), 0.f);
            const float ez = fmaxf(fmaf(fz * i2, g24.z, be24.z), 0.f);
            const float ew = fmaxf(fmaf(fw * i2, g24.w, be24.w), 0.f);
            const float l = quadsum(fmaf(ex, cm.x, fmaf(ey, cm.y, fmaf(ez, cm.z, ew * cm.w))));
            if (qq == 0) slog[pt][s + u][hh] = l + mbw2;
        }
    }
    __syncwarp();

    // ---- softmax over S (per head, redundant across the 4 lanes) ----
    float mx = -1e30f;
#pragma unroll
    for (int s = 0; s < SDIM; s++) mx = fmaxf(mx, slog[pt][s][hh]);
    float se = 0.f;
    float ev[SDIM];
#pragma unroll
    for (int s = 0; s < SDIM; s++) {
        ev[s] = __expf(slog[pt][s][hh] - mx);
        se += ev[s];
    }
    const float rse = 1.f / se;

    // ---- pass 2: out = sum_s (v_g + pe) * w ; pe-part via A = sum_s w_s * a3_s
    float4 acc = make_float4(0.f, 0.f, 0.f, 0.f);
    float A0 = 0.f, A1 = 0.f, A2 = 0.f;
#pragma unroll 2
    for (int s = 0; s < SDIM; s++) {
        const float wg = ev[s] * rse;
        const int j = sidx[pt][s];
        const float4 vg = *(const float4*)(g_v + (size_t)j * CDIM + ch4);
        const float4 a3 = g_a3[n * SDIM + s];
        acc.x = fmaf(vg.x, wg, acc.x);
        acc.y = fmaf(vg.y, wg, acc.y);
        acc.z = fmaf(vg.z, wg, acc.z);
        acc.w = fmaf(vg.w, wg, acc.w);
        A0 = fmaf(a3.x, wg, A0);
        A1 = fmaf(a3.y, wg, A1);
        A2 = fmaf(a3.z, wg, A2);
    }
    float4 o;
    o.x = acc.x + fmaf(A0, wp2c0.x, fmaf(A1, wp2c1.x, fmaf(A2, wp2c2.x, bp24.x)));
    o.y = acc.y + fmaf(A0, wp2c0.y, fmaf(A1, wp2c1.y, fmaf(A2, wp2c2.y, bp24.y)));
    o.z = acc.z + fmaf(A0, wp2c0.z, fmaf(A1, wp2c1.z, fmaf(A2, wp2c2.z, bp24.z)));
    o.w = acc.w + fmaf(A0, wp2c0.w, fmaf(A1, wp2c1.w, fmaf(A2, wp2c2.w, bp24.w)));
    *(float4*)(out + (size_t)n * CDIM + ch4) = o;
}

// ---------------------------------------------------------------------------
extern "C" void kernel_launch(void* const* d_in, const int* in_sizes, int n_in,
                              void* d_out, int out_size)
{
    const float* p      = (const float*)d_in[0];
    const float* x      = (const float*)d_in[1];
    const int*   idx    = (const int*)  d_in[2];
    const float* Wq     = (const float*)d_in[3];
    const float* bq     = (const float*)d_in[4];
    const float* Wk     = (const float*)d_in[5];
    const float* bk     = (const float*)d_in[6];
    const float* Wv     = (const float*)d_in[7];
    const float* bv     = (const float*)d_in[8];
    const float* Wp1    = (const float*)d_in[9];
    const float* bp1    = (const float*)d_in[10];
    const float* gp     = (const float*)d_in[11];
    const float* betap  = (const float*)d_in[12];
    const float* Wp2    = (const float*)d_in[13];
    const float* bp2    = (const float*)d_in[14];
    const float* gw1    = (const float*)d_in[15];
    const float* betaw1 = (const float*)d_in[16];
    const float* Ww1    = (const float*)d_in[17];
    const float* bw1    = (const float*)d_in[18];
    const float* gw2    = (const float*)d_in[19];
    const float* betaw2 = (const float*)d_in[20];
    const float* Ww2    = (const float*)d_in[21];
    const float* bw2    = (const float*)d_in[22];
    float* out = (float*)d_out;

    dim3 gg((NPTS + 127) / 128, 3);
    qkv_gemm_tc<<<gg, 256>>>(x, Wq, bq, Wk, bk, Wv, bv);

    pe_pre<<<(NPTS * SDIM + 255) / 256, 256>>>(p, idx, Wp1, bp1, gp, betap);

    pt_fused<<<NPTS / 8, 256>>>(idx,
                                Wp2, bp2,
                                gw1, betaw1, Ww1, bw1,
                                gw2, betaw2, Ww2, bw2, out);
}